// round 3
// baseline (speedup 1.0000x reference)
#include <cuda_runtime.h>

#define NN 100000
#define EE 1600000
#define HD 32
#define LRELU_S 0.2f
#define PRELU_S 0.1f
#define FULL 0xffffffffu

// ---------------- static device scratch (no allocations allowed) ----------------
__device__ int   g_deg[2][NN];
__device__ int   g_rowptr[2][NN + 1];
__device__ int   g_cursor[2][NN];
__device__ int   g_csr[2][EE];
__device__ float g_h[2][NN * HD];
__device__ float g_al[2][NN];
__device__ float g_ar[2][NN];
__device__ float g_se[NN * HD];
__device__ float g_sk[NN * HD];
__device__ int   g_part[2][32];

#define SCAN_NB ((NN + 4095) / 4096)

// ---------------- launch 1: zero degree arrays ----------------
__global__ void k_zero_deg() {
    int i = blockIdx.x * blockDim.x + threadIdx.x;
    if (i < 2 * NN) ((int*)g_deg)[i] = 0;
}

// ---------------- launch 2: degree histogram (both graphs) ----------------
__global__ void k_degree(const int* __restrict__ d0, const int* __restrict__ d1) {
    int i = blockIdx.x * blockDim.x + threadIdx.x;
    if (i < EE) {
        atomicAdd(&g_deg[0][d0[i]], 1);
        atomicAdd(&g_deg[1][d1[i]], 1);
    }
}

// ---------------- launch 3: per-tile exclusive scan, both graphs ----------------
__global__ void k_scan1(void) {
    __shared__ int sh[512];
    int graph = blockIdx.y;
    const int* deg = g_deg[graph];
    int* out = g_rowptr[graph];
    int base = blockIdx.x * 4096;
    int tid = threadIdx.x;
    int v[8];
    int s = 0;
#pragma unroll
    for (int k = 0; k < 8; k++) {
        int idx = base + tid * 8 + k;
        v[k] = (idx < NN) ? deg[idx] : 0;
        s += v[k];
    }
    sh[tid] = s;
    __syncthreads();
    for (int off = 1; off < 512; off <<= 1) {
        int t = (tid >= off) ? sh[tid - off] : 0;
        __syncthreads();
        sh[tid] += t;
        __syncthreads();
    }
    if (tid == 511) g_part[graph][blockIdx.x] = sh[511];
    int run = (tid > 0) ? sh[tid - 1] : 0;
#pragma unroll
    for (int k = 0; k < 8; k++) {
        int idx = base + tid * 8 + k;
        if (idx < NN) out[idx] = run;
        run += v[k];
    }
}

// ---------------- launch 4: add tile offsets (inline partial-prefix), both graphs ----------------
__global__ void k_scan3(void) {
    __shared__ int sPre[32];
    int graph = blockIdx.y;
    if (threadIdx.x < 32) {
        int lane = threadIdx.x;
        int v = (lane < SCAN_NB) ? g_part[graph][lane] : 0;
        int inc = v;
#pragma unroll
        for (int o = 1; o < 32; o <<= 1) {
            int t = __shfl_up_sync(FULL, inc, o);
            if (lane >= o) inc += t;
        }
        sPre[lane] = inc - v;
    }
    __syncthreads();
    int i = blockIdx.x * blockDim.x + threadIdx.x;
    if (i < NN) {
        int v = g_rowptr[graph][i] + sPre[i >> 12];
        g_rowptr[graph][i] = v;
        g_cursor[graph][i] = v;
    }
    if (i == 0) g_rowptr[graph][NN] = EE;
}

// ---------------- launch 5: CSR fill (both graphs) + layer-0 transform, fused ----------------
#define FILL_BLOCKS ((EE + 255) / 256)
#define T0_BLOCKS   ((NN * 32 + 255) / 256)

__global__ void k_fill_t0(const int* __restrict__ s0, const int* __restrict__ d0,
                          const int* __restrict__ s1, const int* __restrict__ d1,
                          const float* __restrict__ x,
                          const float* __restrict__ Ws, const float* __restrict__ a1s, const float* __restrict__ a2s,
                          const float* __restrict__ Wk, const float* __restrict__ a1k, const float* __restrict__ a2k) {
    if (blockIdx.x < FILL_BLOCKS) {
        int i = blockIdx.x * blockDim.x + threadIdx.x;
        if (i < EE) {
            {
                int d = d0[i];
                int p = atomicAdd(&g_cursor[0][d], 1);
                g_csr[0][p] = s0[i];
            }
            {
                int d = d1[i];
                int p = atomicAdd(&g_cursor[1][d], 1);
                g_csr[1][p] = s1[i];
            }
        }
        return;
    }
    int gtid = (blockIdx.x - FILL_BLOCKS) * blockDim.x + threadIdx.x;
    int w = gtid >> 5;
    int lane = threadIdx.x & 31;
    if (w >= NN) return;
    float xv = x[w];
    float hs = xv * Ws[lane];
    float hk = xv * Wk[lane];
    g_h[0][w * HD + lane] = hs;
    g_h[1][w * HD + lane] = hk;
    float r0 = hs * a1s[lane], r1 = hs * a2s[lane];
    float r2 = hk * a1k[lane], r3 = hk * a2k[lane];
#pragma unroll
    for (int o = 16; o; o >>= 1) {
        r0 += __shfl_xor_sync(FULL, r0, o);
        r1 += __shfl_xor_sync(FULL, r1, o);
        r2 += __shfl_xor_sync(FULL, r2, o);
        r3 += __shfl_xor_sync(FULL, r3, o);
    }
    if (lane == 0) {
        g_al[0][w] = r0;
        g_ar[0][w] = r1;
        g_al[1][w] = r2;
        g_ar[1][w] = r3;
    }
}

// ---------------- GAT aggregation, both graphs fused, batched-MLP gather ----------------
__global__ void __launch_bounds__(256) k_gat_agg(const float* __restrict__ bias0,
                                                 const float* __restrict__ bias1) {
    int w = (blockIdx.x * blockDim.x + threadIdx.x) >> 5;
    int lane = threadIdx.x & 31;
    if (w >= 2 * NN) return;
    int graph = (w >= NN);
    int node = w - graph * NN;
    const int* __restrict__ rp = g_rowptr[graph];
    const int* __restrict__ csr = g_csr[graph];
    const float* __restrict__ al = g_al[graph];
    const float* __restrict__ h = g_h[graph];
    const float* __restrict__ bias = graph ? bias1 : bias0;
    float* __restrict__ out = graph ? g_sk : g_se;

    int start = rp[node], end = rp[node + 1];
    int deg = end - start;
    float arn = g_ar[graph][node];

    // pass 1: online (max, sum-exp); cache first 32 edges in registers
    int s_c = 0;
    float e_c = -1e30f;
    float m = -1e30f, ss = 0.f;
    if (lane < deg) {
        s_c = csr[start + lane];
        float e = al[s_c] + arn;
        e_c = (e >= 0.f) ? e : LRELU_S * e;
        m = e_c;
        ss = 1.f;
    }
    for (int i = start + lane + 32; i < end; i += 32) {
        int s = csr[i];
        float e = al[s] + arn;
        e = (e >= 0.f) ? e : LRELU_S * e;
        if (e > m) {
            ss = ss * __expf(m - e) + 1.f;
            m = e;
        } else {
            ss += __expf(e - m);
        }
    }
#pragma unroll
    for (int o = 16; o; o >>= 1) {
        float mo = __shfl_xor_sync(FULL, m, o);
        float so = __shfl_xor_sync(FULL, ss, o);
        float M = fmaxf(m, mo);
        ss = ss * __expf(m - M) + so * __expf(mo - M);
        m = M;
    }

    // pass 2: weighted gather, 8 loads in flight per batch
    float p_c = __expf(e_c - m);   // 0 for invalid lanes (e_c = -1e30)
    int cnt = (deg < 32) ? deg : 32;
    float acc = 0.f;
    for (int kb = 0; kb < cnt; kb += 8) {
        float pp[8], vv[8];
#pragma unroll
        for (int j = 0; j < 8; j++) {
            int k = kb + j;
            float p = __shfl_sync(FULL, p_c, k & 31);
            int s = __shfl_sync(FULL, s_c, k & 31);
            bool ok = k < cnt;
            pp[j] = ok ? p : 0.f;
            vv[j] = ok ? h[s * HD + lane] : 0.f;
        }
#pragma unroll
        for (int j = 0; j < 8; j++) acc += pp[j] * vv[j];
    }
    // rare slow path: degree > 32
    for (int i = start + 32; i < end; i++) {
        int s = csr[i];
        float e = al[s] + arn;
        e = (e >= 0.f) ? e : LRELU_S * e;
        acc += __expf(e - m) * h[s * HD + lane];
    }
    float res = acc / (ss + 1e-16f) + bias[lane];
    out[node * HD + lane] = (res >= 0.f) ? res : PRELU_S * res;
}

// ---------------- inner node transform: c = se + sk; h = c @ W; al/ar dots ----------------
__global__ void k_transform(const float* __restrict__ Ws, const float* __restrict__ a1s, const float* __restrict__ a2s,
                            const float* __restrict__ Wk, const float* __restrict__ a1k, const float* __restrict__ a2k) {
    __shared__ float sWs[HD * HD];
    __shared__ float sWk[HD * HD];
    for (int i = threadIdx.x; i < HD * HD; i += blockDim.x) {
        sWs[i] = Ws[i];
        sWk[i] = Wk[i];
    }
    __syncthreads();
    int lane = threadIdx.x & 31;
    int n = (blockIdx.x * blockDim.x + threadIdx.x) >> 5;
    if (n >= NN) return;
    float va1s = a1s[lane], va2s = a2s[lane], va1k = a1k[lane], va2k = a2k[lane];
    float cj = g_se[n * HD + lane] + g_sk[n * HD + lane];
    float accS = 0.f, accK = 0.f;
#pragma unroll
    for (int k = 0; k < HD; k++) {
        float ck = __shfl_sync(FULL, cj, k);
        accS += ck * sWs[k * HD + lane];
        accK += ck * sWk[k * HD + lane];
    }
    g_h[0][n * HD + lane] = accS;
    g_h[1][n * HD + lane] = accK;
    float r0 = accS * va1s, r1 = accS * va2s, r2 = accK * va1k, r3 = accK * va2k;
#pragma unroll
    for (int o = 16; o; o >>= 1) {
        r0 += __shfl_xor_sync(FULL, r0, o);
        r1 += __shfl_xor_sync(FULL, r1, o);
        r2 += __shfl_xor_sync(FULL, r2, o);
        r3 += __shfl_xor_sync(FULL, r3, o);
    }
    if (lane == 0) {
        g_al[0][n] = r0;
        g_ar[0][n] = r1;
        g_al[1][n] = r2;
        g_ar[1][n] = r3;
    }
}

// ---------------- final head: dim0 MLPs + edge_neighbor (batched) + dim1 MLP ----------------
__global__ void __launch_bounds__(256) k_final(const float* __restrict__ x,
                        const float* __restrict__ Wos, const float* __restrict__ bos,
                        const float* __restrict__ Wok, const float* __restrict__ bok,
                        const float* __restrict__ Wd1, const float* __restrict__ bd1,
                        float* __restrict__ out) {
    int w = (blockIdx.x * blockDim.x + threadIdx.x) >> 5;
    int lane = threadIdx.x & 31;
    if (w >= NN) return;

    float c0 = g_se[w * HD + lane];
    float c1 = g_sk[w * HD + lane];

    // final_dim0 dots
    float d00 = c0 * Wos[lane * 2]     + c1 * Wos[(HD + lane) * 2];
    float d01 = c0 * Wos[lane * 2 + 1] + c1 * Wos[(HD + lane) * 2 + 1];
    float d10 = c0 * Wok[lane * 2]     + c1 * Wok[(HD + lane) * 2];
    float d11 = c0 * Wok[lane * 2 + 1] + c1 * Wok[(HD + lane) * 2 + 1];
#pragma unroll
    for (int o = 16; o; o >>= 1) {
        d00 += __shfl_xor_sync(FULL, d00, o);
        d01 += __shfl_xor_sync(FULL, d01, o);
        d10 += __shfl_xor_sync(FULL, d10, o);
        d11 += __shfl_xor_sync(FULL, d11, o);
    }

    // edge_neighbor over source graph — register cache + batched loads
    int st0 = g_rowptr[0][w], en0 = g_rowptr[0][w + 1];
    int deg0 = en0 - st0;
    int s0c = 0; float x0c = 0.f;
    if (lane < deg0) { s0c = g_csr[0][st0 + lane]; x0c = x[s0c]; }
    int cnt0 = (deg0 < 32) ? deg0 : 32;
    float a0 = 0.f, a1v = 0.f;
    for (int kb = 0; kb < cnt0; kb += 8) {
        float xp[8], vs[8], vk[8];
#pragma unroll
        for (int j = 0; j < 8; j++) {
            int k = kb + j;
            int s = __shfl_sync(FULL, s0c, k & 31);
            float xs = __shfl_sync(FULL, x0c, k & 31);
            bool ok = k < cnt0;
            xp[j] = ok ? xs : 0.f;
            vs[j] = ok ? g_se[s * HD + lane] : 0.f;
            vk[j] = ok ? g_sk[s * HD + lane] : 0.f;
        }
#pragma unroll
        for (int j = 0; j < 8; j++) { a0 += xp[j] * vs[j]; a1v += xp[j] * vk[j]; }
    }
    for (int i = st0 + 32; i < en0; i++) {
        int s = g_csr[0][i];
        float xs = x[s];
        a0  += xs * g_se[s * HD + lane];
        a1v += xs * g_sk[s * HD + lane];
    }
    float e1s0 = a0 + 0.5f * c0;  e1s0 = (e1s0 > 0.f) ? e1s0 : 0.f;
    float e1s1 = a1v + 0.5f * c1; e1s1 = (e1s1 > 0.f) ? e1s1 : 0.f;

    // edge_neighbor over sink graph
    int st1 = g_rowptr[1][w], en1 = g_rowptr[1][w + 1];
    int deg1 = en1 - st1;
    int s1c = 0; float x1c = 0.f;
    if (lane < deg1) { s1c = g_csr[1][st1 + lane]; x1c = x[s1c]; }
    int cnt1 = (deg1 < 32) ? deg1 : 32;
    float b0 = 0.f, b1v = 0.f;
    for (int kb = 0; kb < cnt1; kb += 8) {
        float xp[8], vs[8], vk[8];
#pragma unroll
        for (int j = 0; j < 8; j++) {
            int k = kb + j;
            int s = __shfl_sync(FULL, s1c, k & 31);
            float xs = __shfl_sync(FULL, x1c, k & 31);
            bool ok = k < cnt1;
            xp[j] = ok ? xs : 0.f;
            vs[j] = ok ? g_se[s * HD + lane] : 0.f;
            vk[j] = ok ? g_sk[s * HD + lane] : 0.f;
        }
#pragma unroll
        for (int j = 0; j < 8; j++) { b0 += xp[j] * vs[j]; b1v += xp[j] * vk[j]; }
    }
    for (int i = st1 + 32; i < en1; i++) {
        int s = g_csr[1][i];
        float xs = x[s];
        b0  += xs * g_se[s * HD + lane];
        b1v += xs * g_sk[s * HD + lane];
    }
    float e1k0 = b0 + 0.5f * c0;  e1k0 = (e1k0 > 0.f) ? e1k0 : 0.f;
    float e1k1 = b1v + 0.5f * c1; e1k1 = (e1k1 > 0.f) ? e1k1 : 0.f;

    float t0 = e1s0 + e1k0;
    float t1 = e1s1 + e1k1;
    float g0 = t0 * Wd1[lane * 2]     + t1 * Wd1[(HD + lane) * 2];
    float g1 = t0 * Wd1[lane * 2 + 1] + t1 * Wd1[(HD + lane) * 2 + 1];
#pragma unroll
    for (int o = 16; o; o >>= 1) {
        g0 += __shfl_xor_sync(FULL, g0, o);
        g1 += __shfl_xor_sync(FULL, g1, o);
    }

    if (lane == 0) {
        float s0 = d00 + bos[0]; s0 = (s0 > 0.f) ? s0 : 0.f;
        float s1 = d01 + bos[1]; s1 = (s1 > 0.f) ? s1 : 0.f;
        float k0 = d10 + bok[0]; k0 = (k0 > 0.f) ? k0 : 0.f;
        float k1 = d11 + bok[1]; k1 = (k1 > 0.f) ? k1 : 0.f;
        out[w * 4 + 0] = 0.5f * (s0 + k0);
        out[w * 4 + 1] = 0.5f * (s1 + k1);
        float f2 = g0 + bd1[0];
        float f3 = g1 + bd1[1];
        out[w * 4 + 2] = (f2 > 0.f) ? f2 : 0.f;
        out[w * 4 + 3] = (f3 > 0.f) ? f3 : 0.f;
    }
}

// ---------------- launch ----------------
extern "C" void kernel_launch(void* const* d_in, const int* in_sizes, int n_in,
                              void* d_out, int out_size) {
    const float* x        = (const float*)d_in[0];
    const int*   sei      = (const int*)d_in[1];
    const int*   kei      = (const int*)d_in[2];
    const float* W_in_src = (const float*)d_in[3];
    const float* b_in_src = (const float*)d_in[4];
    const float* a1_in_src= (const float*)d_in[5];
    const float* a2_in_src= (const float*)d_in[6];
    const float* W_in_snk = (const float*)d_in[7];
    const float* b_in_snk = (const float*)d_in[8];
    const float* a1_in_snk= (const float*)d_in[9];
    const float* a2_in_snk= (const float*)d_in[10];
    const float* W_src    = (const float*)d_in[11];
    const float* b_src    = (const float*)d_in[12];
    const float* a1_src   = (const float*)d_in[13];
    const float* a2_src   = (const float*)d_in[14];
    const float* W_snk    = (const float*)d_in[15];
    const float* b_snk    = (const float*)d_in[16];
    const float* a1_snk   = (const float*)d_in[17];
    const float* a2_snk   = (const float*)d_in[18];
    const float* W_o_src  = (const float*)d_in[19];
    const float* b_o_src  = (const float*)d_in[20];
    const float* W_o_snk  = (const float*)d_in[21];
    const float* b_o_snk  = (const float*)d_in[22];
    const float* W_d1     = (const float*)d_in[23];
    const float* b_d1     = (const float*)d_in[24];
    float* out = (float*)d_out;

    const int* s0 = sei;
    const int* dd0 = sei + EE;
    const int* s1 = kei;
    const int* dd1 = kei + EE;

    const int TB = 256;

    k_zero_deg<<<(2 * NN + TB - 1) / TB, TB>>>();
    k_degree<<<(EE + TB - 1) / TB, TB>>>(dd0, dd1);
    {
        dim3 g(SCAN_NB, 2);
        k_scan1<<<g, 512>>>();
    }
    {
        dim3 g((NN + TB - 1) / TB, 2);
        k_scan3<<<g, TB>>>();
    }
    k_fill_t0<<<FILL_BLOCKS + T0_BLOCKS, TB>>>(s0, dd0, s1, dd1, x,
                                               W_in_src, a1_in_src, a2_in_src,
                                               W_in_snk, a1_in_snk, a2_in_snk);

    int agg_blocks = (2 * NN * 32 + TB - 1) / TB;
    int node_blocks = (NN * 32 + TB - 1) / TB;

    k_gat_agg<<<agg_blocks, TB>>>(b_in_src, b_in_snk);

    for (int i = 0; i < 4; i++) {
        k_transform<<<node_blocks, TB>>>(W_src + i * HD * HD, a1_src + i * HD, a2_src + i * HD,
                                         W_snk + i * HD * HD, a1_snk + i * HD, a2_snk + i * HD);
        k_gat_agg<<<agg_blocks, TB>>>(b_src + i * HD, b_snk + i * HD);
    }

    k_final<<<node_blocks, TB>>>(x, W_o_src, b_o_src, W_o_snk, b_o_snk, W_d1, b_d1, out);
}

// round 4
// speedup vs baseline: 1.2195x; 1.2195x over previous
#include <cuda_runtime.h>

#define NN 100000
#define EE 1600000
#define HD 32
#define LRELU_S 0.2f
#define PRELU_S 0.1f
#define FULL 0xffffffffu

// ---------------- cp.async helpers ----------------
__device__ __forceinline__ void cp_async16(void* smem_dst, const void* gmem_src) {
    unsigned sa = (unsigned)__cvta_generic_to_shared(smem_dst);
    asm volatile("cp.async.cg.shared.global [%0], [%1], 16;\n" :: "r"(sa), "l"(gmem_src) : "memory");
}
__device__ __forceinline__ void cp_commit() { asm volatile("cp.async.commit_group;\n" ::: "memory"); }
__device__ __forceinline__ void cp_wait0()  { asm volatile("cp.async.wait_group 0;\n" ::: "memory"); }

// ---------------- static device scratch (no allocations allowed) ----------------
__device__ int   g_deg[2][NN];
__device__ int   g_rowptr[2][NN + 1];
__device__ int   g_cursor[2][NN];
__device__ int   g_csr[2][EE];
__device__ float g_h[2][NN * HD];
__device__ float g_al[2][NN];
__device__ float g_ar[2][NN];
__device__ float g_se[NN * HD];
__device__ float g_sk[NN * HD];
__device__ int   g_part[2][32];

#define SCAN_NB ((NN + 4095) / 4096)

// ---------------- launch 1: zero degree arrays ----------------
__global__ void k_zero_deg() {
    int i = blockIdx.x * blockDim.x + threadIdx.x;
    if (i < 2 * NN) ((int*)g_deg)[i] = 0;
}

// ---------------- launch 2: degree histogram (both graphs) ----------------
__global__ void k_degree(const int* __restrict__ d0, const int* __restrict__ d1) {
    int i = blockIdx.x * blockDim.x + threadIdx.x;
    if (i < EE) {
        atomicAdd(&g_deg[0][d0[i]], 1);
        atomicAdd(&g_deg[1][d1[i]], 1);
    }
}

// ---------------- launch 3: per-tile exclusive scan, both graphs ----------------
__global__ void k_scan1(void) {
    __shared__ int sh[512];
    int graph = blockIdx.y;
    const int* deg = g_deg[graph];
    int* out = g_rowptr[graph];
    int base = blockIdx.x * 4096;
    int tid = threadIdx.x;
    int v[8];
    int s = 0;
#pragma unroll
    for (int k = 0; k < 8; k++) {
        int idx = base + tid * 8 + k;
        v[k] = (idx < NN) ? deg[idx] : 0;
        s += v[k];
    }
    sh[tid] = s;
    __syncthreads();
    for (int off = 1; off < 512; off <<= 1) {
        int t = (tid >= off) ? sh[tid - off] : 0;
        __syncthreads();
        sh[tid] += t;
        __syncthreads();
    }
    if (tid == 511) g_part[graph][blockIdx.x] = sh[511];
    int run = (tid > 0) ? sh[tid - 1] : 0;
#pragma unroll
    for (int k = 0; k < 8; k++) {
        int idx = base + tid * 8 + k;
        if (idx < NN) out[idx] = run;
        run += v[k];
    }
}

// ---------------- launch 4: add tile offsets, both graphs ----------------
__global__ void k_scan3(void) {
    __shared__ int sPre[32];
    int graph = blockIdx.y;
    if (threadIdx.x < 32) {
        int lane = threadIdx.x;
        int v = (lane < SCAN_NB) ? g_part[graph][lane] : 0;
        int inc = v;
#pragma unroll
        for (int o = 1; o < 32; o <<= 1) {
            int t = __shfl_up_sync(FULL, inc, o);
            if (lane >= o) inc += t;
        }
        sPre[lane] = inc - v;
    }
    __syncthreads();
    int i = blockIdx.x * blockDim.x + threadIdx.x;
    if (i < NN) {
        int v = g_rowptr[graph][i] + sPre[i >> 12];
        g_rowptr[graph][i] = v;
        g_cursor[graph][i] = v;
    }
    if (i == 0) g_rowptr[graph][NN] = EE;
}

// ---------------- launch 5: CSR fill (both graphs) + layer-0 transform, fused ----------------
#define FILL_BLOCKS ((EE + 255) / 256)
#define T0_BLOCKS   ((NN * 32 + 255) / 256)

__global__ void k_fill_t0(const int* __restrict__ s0, const int* __restrict__ d0,
                          const int* __restrict__ s1, const int* __restrict__ d1,
                          const float* __restrict__ x,
                          const float* __restrict__ Ws, const float* __restrict__ a1s, const float* __restrict__ a2s,
                          const float* __restrict__ Wk, const float* __restrict__ a1k, const float* __restrict__ a2k) {
    if (blockIdx.x < FILL_BLOCKS) {
        int i = blockIdx.x * blockDim.x + threadIdx.x;
        if (i < EE) {
            {
                int d = d0[i];
                int p = atomicAdd(&g_cursor[0][d], 1);
                g_csr[0][p] = s0[i];
            }
            {
                int d = d1[i];
                int p = atomicAdd(&g_cursor[1][d], 1);
                g_csr[1][p] = s1[i];
            }
        }
        return;
    }
    int gtid = (blockIdx.x - FILL_BLOCKS) * blockDim.x + threadIdx.x;
    int w = gtid >> 5;
    int lane = threadIdx.x & 31;
    if (w >= NN) return;
    float xv = x[w];
    float hs = xv * Ws[lane];
    float hk = xv * Wk[lane];
    g_h[0][w * HD + lane] = hs;
    g_h[1][w * HD + lane] = hk;
    float r0 = hs * a1s[lane], r1 = hs * a2s[lane];
    float r2 = hk * a1k[lane], r3 = hk * a2k[lane];
#pragma unroll
    for (int o = 16; o; o >>= 1) {
        r0 += __shfl_xor_sync(FULL, r0, o);
        r1 += __shfl_xor_sync(FULL, r1, o);
        r2 += __shfl_xor_sync(FULL, r2, o);
        r3 += __shfl_xor_sync(FULL, r3, o);
    }
    if (lane == 0) {
        g_al[0][w] = r0;
        g_ar[0][w] = r1;
        g_al[1][w] = r2;
        g_ar[1][w] = r3;
    }
}

// ---------------- GAT aggregation: cp.async row staging into smem ----------------
__global__ void __launch_bounds__(256) k_gat_agg(const float* __restrict__ bias0,
                                                 const float* __restrict__ bias1) {
    __shared__ float sv[8][32][HD];   // 32KB: staged h rows per warp
    __shared__ float sp[8][32];       // softmax weights per warp
    int wid = threadIdx.x >> 5;
    int lane = threadIdx.x & 31;
    int w = (blockIdx.x * blockDim.x + threadIdx.x) >> 5;
    if (w >= 2 * NN) return;
    int graph = (w >= NN);
    int node = w - graph * NN;
    const int* __restrict__ rp = g_rowptr[graph];
    const int* __restrict__ csr = g_csr[graph];
    const float* __restrict__ al = g_al[graph];
    const float* __restrict__ h = g_h[graph];
    const float* __restrict__ bias = graph ? bias1 : bias0;
    float* __restrict__ out = graph ? g_sk : g_se;

    int start = rp[node], end = rp[node + 1];
    int deg = end - start;
    float arn = g_ar[graph][node];

    // pass 1: online (max, sum-exp); cache first 32 edges in registers
    int s_c = 0;
    float e_c = -1e30f;
    float m = -1e30f, ss = 0.f;
    if (lane < deg) {
        s_c = csr[start + lane];
        float e = al[s_c] + arn;
        e_c = (e >= 0.f) ? e : LRELU_S * e;
        m = e_c;
        ss = 1.f;
    }
    for (int i = start + lane + 32; i < end; i += 32) {
        int s = csr[i];
        float e = al[s] + arn;
        e = (e >= 0.f) ? e : LRELU_S * e;
        if (e > m) {
            ss = ss * __expf(m - e) + 1.f;
            m = e;
        } else {
            ss += __expf(e - m);
        }
    }
#pragma unroll
    for (int o = 16; o; o >>= 1) {
        float mo = __shfl_xor_sync(FULL, m, o);
        float so = __shfl_xor_sync(FULL, ss, o);
        float M = fmaxf(m, mo);
        ss = ss * __expf(m - M) + so * __expf(mo - M);
        m = M;
    }

    // stage weights + rows
    sp[wid][lane] = (lane < deg) ? __expf(e_c - m) : 0.f;
    int cnt = (deg < 32) ? deg : 32;
    int r = lane >> 3;           // row quarter 0..3
    int c = (lane & 7) * 4;      // 16B chunk within row (in floats)
#pragma unroll
    for (int j = 0; j < 8; j++) {
        int row = j * 4 + r;
        int s = __shfl_sync(FULL, s_c, row);
        if (row < cnt) cp_async16(&sv[wid][row][c], &h[s * HD + c]);
    }
    cp_commit();
    cp_wait0();
    __syncwarp();

    // consume: conflict-free LDS + FMA
    float acc = 0.f;
    for (int k = 0; k < cnt; k++) {
        acc += sp[wid][k] * sv[wid][k][lane];
    }
    // rare slow path: degree > 32
    for (int i = start + 32; i < end; i++) {
        int s = csr[i];
        float e = al[s] + arn;
        e = (e >= 0.f) ? e : LRELU_S * e;
        acc += __expf(e - m) * h[s * HD + lane];
    }
    float res = acc / (ss + 1e-16f) + bias[lane];
    out[node * HD + lane] = (res >= 0.f) ? res : PRELU_S * res;
}

// ---------------- inner node transform: c = se + sk; h = c @ W; al/ar dots ----------------
__global__ void k_transform(const float* __restrict__ Ws, const float* __restrict__ a1s, const float* __restrict__ a2s,
                            const float* __restrict__ Wk, const float* __restrict__ a1k, const float* __restrict__ a2k) {
    __shared__ float sWs[HD * HD];
    __shared__ float sWk[HD * HD];
    for (int i = threadIdx.x; i < HD * HD; i += blockDim.x) {
        sWs[i] = Ws[i];
        sWk[i] = Wk[i];
    }
    __syncthreads();
    int lane = threadIdx.x & 31;
    int n = (blockIdx.x * blockDim.x + threadIdx.x) >> 5;
    if (n >= NN) return;
    float va1s = a1s[lane], va2s = a2s[lane], va1k = a1k[lane], va2k = a2k[lane];
    float cj = g_se[n * HD + lane] + g_sk[n * HD + lane];
    float accS = 0.f, accK = 0.f;
#pragma unroll
    for (int k = 0; k < HD; k++) {
        float ck = __shfl_sync(FULL, cj, k);
        accS += ck * sWs[k * HD + lane];
        accK += ck * sWk[k * HD + lane];
    }
    g_h[0][n * HD + lane] = accS;
    g_h[1][n * HD + lane] = accK;
    float r0 = accS * va1s, r1 = accS * va2s, r2 = accK * va1k, r3 = accK * va2k;
#pragma unroll
    for (int o = 16; o; o >>= 1) {
        r0 += __shfl_xor_sync(FULL, r0, o);
        r1 += __shfl_xor_sync(FULL, r1, o);
        r2 += __shfl_xor_sync(FULL, r2, o);
        r3 += __shfl_xor_sync(FULL, r3, o);
    }
    if (lane == 0) {
        g_al[0][n] = r0;
        g_ar[0][n] = r1;
        g_al[1][n] = r2;
        g_ar[1][n] = r3;
    }
}

// ---------------- final head: staged edge_neighbor + MLPs ----------------
__global__ void __launch_bounds__(256) k_final(const float* __restrict__ x,
                        const float* __restrict__ Wos, const float* __restrict__ bos,
                        const float* __restrict__ Wok, const float* __restrict__ bok,
                        const float* __restrict__ Wd1, const float* __restrict__ bd1,
                        float* __restrict__ out) {
    __shared__ float sv[8][32][HD];
    __shared__ float sp[8][32];
    int wid = threadIdx.x >> 5;
    int lane = threadIdx.x & 31;
    int w = (blockIdx.x * blockDim.x + threadIdx.x) >> 5;
    if (w >= NN) return;

    float c0 = g_se[w * HD + lane];
    float c1 = g_sk[w * HD + lane];

    // final_dim0 dots
    float d00 = c0 * Wos[lane * 2]     + c1 * Wos[(HD + lane) * 2];
    float d01 = c0 * Wos[lane * 2 + 1] + c1 * Wos[(HD + lane) * 2 + 1];
    float d10 = c0 * Wok[lane * 2]     + c1 * Wok[(HD + lane) * 2];
    float d11 = c0 * Wok[lane * 2 + 1] + c1 * Wok[(HD + lane) * 2 + 1];
#pragma unroll
    for (int o = 16; o; o >>= 1) {
        d00 += __shfl_xor_sync(FULL, d00, o);
        d01 += __shfl_xor_sync(FULL, d01, o);
        d10 += __shfl_xor_sync(FULL, d10, o);
        d11 += __shfl_xor_sync(FULL, d11, o);
    }

    int r = lane >> 3;
    int c = (lane & 7) * 4;

    float aggS[2], aggK[2];   // per graph
#pragma unroll
    for (int g = 0; g < 2; g++) {
        const int* __restrict__ csr = g_csr[g];
        int st = g_rowptr[g][w], en = g_rowptr[g][w + 1];
        int deg = en - st;
        int cnt = (deg < 32) ? deg : 32;
        int s_c = 0; float x_c = 0.f;
        if (lane < deg) { s_c = csr[st + lane]; x_c = x[s_c]; }
        sp[wid][lane] = x_c;

        // phase A: se rows
#pragma unroll
        for (int j = 0; j < 8; j++) {
            int row = j * 4 + r;
            int s = __shfl_sync(FULL, s_c, row);
            if (row < cnt) cp_async16(&sv[wid][row][c], &g_se[s * HD + c]);
        }
        cp_commit();
        cp_wait0();
        __syncwarp();
        float a0 = 0.f;
        for (int k = 0; k < cnt; k++) a0 += sp[wid][k] * sv[wid][k][lane];
        __syncwarp();

        // phase B: sk rows
#pragma unroll
        for (int j = 0; j < 8; j++) {
            int row = j * 4 + r;
            int s = __shfl_sync(FULL, s_c, row);
            if (row < cnt) cp_async16(&sv[wid][row][c], &g_sk[s * HD + c]);
        }
        cp_commit();
        cp_wait0();
        __syncwarp();
        float a1v = 0.f;
        for (int k = 0; k < cnt; k++) a1v += sp[wid][k] * sv[wid][k][lane];
        __syncwarp();

        // slow path: degree > 32
        for (int i = st + 32; i < en; i++) {
            int s = csr[i];
            float xs = x[s];
            a0  += xs * g_se[s * HD + lane];
            a1v += xs * g_sk[s * HD + lane];
        }
        aggS[g] = a0;
        aggK[g] = a1v;
    }

    float e1s0 = aggS[0] + 0.5f * c0;  e1s0 = (e1s0 > 0.f) ? e1s0 : 0.f;
    float e1s1 = aggK[0] + 0.5f * c1;  e1s1 = (e1s1 > 0.f) ? e1s1 : 0.f;
    float e1k0 = aggS[1] + 0.5f * c0;  e1k0 = (e1k0 > 0.f) ? e1k0 : 0.f;
    float e1k1 = aggK[1] + 0.5f * c1;  e1k1 = (e1k1 > 0.f) ? e1k1 : 0.f;

    float t0 = e1s0 + e1k0;
    float t1 = e1s1 + e1k1;
    float g0 = t0 * Wd1[lane * 2]     + t1 * Wd1[(HD + lane) * 2];
    float g1 = t0 * Wd1[lane * 2 + 1] + t1 * Wd1[(HD + lane) * 2 + 1];
#pragma unroll
    for (int o = 16; o; o >>= 1) {
        g0 += __shfl_xor_sync(FULL, g0, o);
        g1 += __shfl_xor_sync(FULL, g1, o);
    }

    if (lane == 0) {
        float s0 = d00 + bos[0]; s0 = (s0 > 0.f) ? s0 : 0.f;
        float s1 = d01 + bos[1]; s1 = (s1 > 0.f) ? s1 : 0.f;
        float k0 = d10 + bok[0]; k0 = (k0 > 0.f) ? k0 : 0.f;
        float k1 = d11 + bok[1]; k1 = (k1 > 0.f) ? k1 : 0.f;
        out[w * 4 + 0] = 0.5f * (s0 + k0);
        out[w * 4 + 1] = 0.5f * (s1 + k1);
        float f2 = g0 + bd1[0];
        float f3 = g1 + bd1[1];
        out[w * 4 + 2] = (f2 > 0.f) ? f2 : 0.f;
        out[w * 4 + 3] = (f3 > 0.f) ? f3 : 0.f;
    }
}

// ---------------- launch ----------------
extern "C" void kernel_launch(void* const* d_in, const int* in_sizes, int n_in,
                              void* d_out, int out_size) {
    const float* x        = (const float*)d_in[0];
    const int*   sei      = (const int*)d_in[1];
    const int*   kei      = (const int*)d_in[2];
    const float* W_in_src = (const float*)d_in[3];
    const float* b_in_src = (const float*)d_in[4];
    const float* a1_in_src= (const float*)d_in[5];
    const float* a2_in_src= (const float*)d_in[6];
    const float* W_in_snk = (const float*)d_in[7];
    const float* b_in_snk = (const float*)d_in[8];
    const float* a1_in_snk= (const float*)d_in[9];
    const float* a2_in_snk= (const float*)d_in[10];
    const float* W_src    = (const float*)d_in[11];
    const float* b_src    = (const float*)d_in[12];
    const float* a1_src   = (const float*)d_in[13];
    const float* a2_src   = (const float*)d_in[14];
    const float* W_snk    = (const float*)d_in[15];
    const float* b_snk    = (const float*)d_in[16];
    const float* a1_snk   = (const float*)d_in[17];
    const float* a2_snk   = (const float*)d_in[18];
    const float* W_o_src  = (const float*)d_in[19];
    const float* b_o_src  = (const float*)d_in[20];
    const float* W_o_snk  = (const float*)d_in[21];
    const float* b_o_snk  = (const float*)d_in[22];
    const float* W_d1     = (const float*)d_in[23];
    const float* b_d1     = (const float*)d_in[24];
    float* out = (float*)d_out;

    const int* s0 = sei;
    const int* dd0 = sei + EE;
    const int* s1 = kei;
    const int* dd1 = kei + EE;

    const int TB = 256;

    k_zero_deg<<<(2 * NN + TB - 1) / TB, TB>>>();
    k_degree<<<(EE + TB - 1) / TB, TB>>>(dd0, dd1);
    {
        dim3 g(SCAN_NB, 2);
        k_scan1<<<g, 512>>>();
    }
    {
        dim3 g((NN + TB - 1) / TB, 2);
        k_scan3<<<g, TB>>>();
    }
    k_fill_t0<<<FILL_BLOCKS + T0_BLOCKS, TB>>>(s0, dd0, s1, dd1, x,
                                               W_in_src, a1_in_src, a2_in_src,
                                               W_in_snk, a1_in_snk, a2_in_snk);

    int agg_blocks = (2 * NN * 32 + TB - 1) / TB;
    int node_blocks = (NN * 32 + TB - 1) / TB;

    k_gat_agg<<<agg_blocks, TB>>>(b_in_src, b_in_snk);

    for (int i = 0; i < 4; i++) {
        k_transform<<<node_blocks, TB>>>(W_src + i * HD * HD, a1_src + i * HD, a2_src + i * HD,
                                         W_snk + i * HD * HD, a1_snk + i * HD, a2_snk + i * HD);
        k_gat_agg<<<agg_blocks, TB>>>(b_src + i * HD, b_snk + i * HD);
    }

    k_final<<<node_blocks, TB>>>(x, W_o_src, b_o_src, W_o_snk, b_o_snk, W_d1, b_d1, out);
}

// round 5
// speedup vs baseline: 1.3071x; 1.0719x over previous
#include <cuda_runtime.h>
#include <cuda_fp16.h>

#define NN 100000
#define EE 1600000
#define HD 32
#define LRELU_S 0.2f
#define PRELU_S 0.1f
#define FULL 0xffffffffu

// ---------------- cp.async helpers ----------------
__device__ __forceinline__ void cp_async16(void* smem_dst, const void* gmem_src) {
    unsigned sa = (unsigned)__cvta_generic_to_shared(smem_dst);
    asm volatile("cp.async.cg.shared.global [%0], [%1], 16;\n" :: "r"(sa), "l"(gmem_src) : "memory");
}
__device__ __forceinline__ void cp_commit() { asm volatile("cp.async.commit_group;\n" ::: "memory"); }
__device__ __forceinline__ void cp_wait0()  { asm volatile("cp.async.wait_group 0;\n" ::: "memory"); }

// ---------------- static device scratch (no allocations allowed) ----------------
__device__ int    g_deg[2][NN];
__device__ int    g_rowptr[2][NN + 1];
__device__ int    g_cursor[2][NN];
__device__ int    g_csr[2][EE];
__device__ __half g_hh[2][NN * HD];      // fp16 message values
__device__ float  g_al[2][NN];
__device__ float  g_ar[2][NN];
__device__ float  g_se[NN * HD];
__device__ float  g_sk[NN * HD];
__device__ __half g_cc[NN][2 * HD];      // packed fp16 [se|sk] for final head
__device__ int    g_part[2][32];

#define SCAN_NB ((NN + 4095) / 4096)

// ---------------- launch 1: zero degree arrays ----------------
__global__ void k_zero_deg() {
    int i = blockIdx.x * blockDim.x + threadIdx.x;
    if (i < 2 * NN) ((int*)g_deg)[i] = 0;
}

// ---------------- launch 2: degree histogram (both graphs) ----------------
__global__ void k_degree(const int* __restrict__ d0, const int* __restrict__ d1) {
    int i = blockIdx.x * blockDim.x + threadIdx.x;
    if (i < EE) {
        atomicAdd(&g_deg[0][d0[i]], 1);
        atomicAdd(&g_deg[1][d1[i]], 1);
    }
}

// ---------------- launch 3: per-tile exclusive scan, both graphs ----------------
__global__ void k_scan1(void) {
    __shared__ int sh[512];
    int graph = blockIdx.y;
    const int* deg = g_deg[graph];
    int* out = g_rowptr[graph];
    int base = blockIdx.x * 4096;
    int tid = threadIdx.x;
    int v[8];
    int s = 0;
#pragma unroll
    for (int k = 0; k < 8; k++) {
        int idx = base + tid * 8 + k;
        v[k] = (idx < NN) ? deg[idx] : 0;
        s += v[k];
    }
    sh[tid] = s;
    __syncthreads();
    for (int off = 1; off < 512; off <<= 1) {
        int t = (tid >= off) ? sh[tid - off] : 0;
        __syncthreads();
        sh[tid] += t;
        __syncthreads();
    }
    if (tid == 511) g_part[graph][blockIdx.x] = sh[511];
    int run = (tid > 0) ? sh[tid - 1] : 0;
#pragma unroll
    for (int k = 0; k < 8; k++) {
        int idx = base + tid * 8 + k;
        if (idx < NN) out[idx] = run;
        run += v[k];
    }
}

// ---------------- launch 4: add tile offsets, both graphs ----------------
__global__ void k_scan3(void) {
    __shared__ int sPre[32];
    int graph = blockIdx.y;
    if (threadIdx.x < 32) {
        int lane = threadIdx.x;
        int v = (lane < SCAN_NB) ? g_part[graph][lane] : 0;
        int inc = v;
#pragma unroll
        for (int o = 1; o < 32; o <<= 1) {
            int t = __shfl_up_sync(FULL, inc, o);
            if (lane >= o) inc += t;
        }
        sPre[lane] = inc - v;
    }
    __syncthreads();
    int i = blockIdx.x * blockDim.x + threadIdx.x;
    if (i < NN) {
        int v = g_rowptr[graph][i] + sPre[i >> 12];
        g_rowptr[graph][i] = v;
        g_cursor[graph][i] = v;
    }
    if (i == 0) g_rowptr[graph][NN] = EE;
}

// ---------------- launch 5: CSR fill (both graphs) + layer-0 transform, fused ----------------
#define FILL_BLOCKS ((EE + 255) / 256)
#define T0_BLOCKS   ((NN * 32 + 255) / 256)

__global__ void k_fill_t0(const int* __restrict__ s0, const int* __restrict__ d0,
                          const int* __restrict__ s1, const int* __restrict__ d1,
                          const float* __restrict__ x,
                          const float* __restrict__ Ws, const float* __restrict__ a1s, const float* __restrict__ a2s,
                          const float* __restrict__ Wk, const float* __restrict__ a1k, const float* __restrict__ a2k) {
    if (blockIdx.x < FILL_BLOCKS) {
        int i = blockIdx.x * blockDim.x + threadIdx.x;
        if (i < EE) {
            {
                int d = d0[i];
                int p = atomicAdd(&g_cursor[0][d], 1);
                g_csr[0][p] = s0[i];
            }
            {
                int d = d1[i];
                int p = atomicAdd(&g_cursor[1][d], 1);
                g_csr[1][p] = s1[i];
            }
        }
        return;
    }
    int gtid = (blockIdx.x - FILL_BLOCKS) * blockDim.x + threadIdx.x;
    int w = gtid >> 5;
    int lane = threadIdx.x & 31;
    if (w >= NN) return;
    float xv = x[w];
    float hs = xv * Ws[lane];
    float hk = xv * Wk[lane];
    g_hh[0][w * HD + lane] = __float2half(hs);
    g_hh[1][w * HD + lane] = __float2half(hk);
    float r0 = hs * a1s[lane], r1 = hs * a2s[lane];
    float r2 = hk * a1k[lane], r3 = hk * a2k[lane];
#pragma unroll
    for (int o = 16; o; o >>= 1) {
        r0 += __shfl_xor_sync(FULL, r0, o);
        r1 += __shfl_xor_sync(FULL, r1, o);
        r2 += __shfl_xor_sync(FULL, r2, o);
        r3 += __shfl_xor_sync(FULL, r3, o);
    }
    if (lane == 0) {
        g_al[0][w] = r0;
        g_ar[0][w] = r1;
        g_al[1][w] = r2;
        g_ar[1][w] = r3;
    }
}

// ---------------- GAT aggregation: cp.async fp16 row staging ----------------
// write_cc: also emit packed fp16 [se|sk] rows (only for last layer)
__global__ void __launch_bounds__(256) k_gat_agg(const float* __restrict__ bias0,
                                                 const float* __restrict__ bias1,
                                                 int write_cc) {
    __shared__ __half svh[8][32][HD];   // 16KB: staged fp16 h rows per warp
    __shared__ float  sp[8][32];        // softmax weights per warp
    int wid = threadIdx.x >> 5;
    int lane = threadIdx.x & 31;
    int w = (blockIdx.x * blockDim.x + threadIdx.x) >> 5;
    if (w >= 2 * NN) return;
    int graph = (w >= NN);
    int node = w - graph * NN;
    const int* __restrict__ rp = g_rowptr[graph];
    const int* __restrict__ csr = g_csr[graph];
    const float* __restrict__ al = g_al[graph];
    const __half* __restrict__ hh = g_hh[graph];
    const float* __restrict__ bias = graph ? bias1 : bias0;
    float* __restrict__ out = graph ? g_sk : g_se;

    int start = rp[node], end = rp[node + 1];
    int deg = end - start;
    float arn = g_ar[graph][node];

    // pass 1: online (max, sum-exp); cache first 32 edges in registers
    int s_c = 0;
    float e_c = -1e30f;
    float m = -1e30f, ss = 0.f;
    if (lane < deg) {
        s_c = csr[start + lane];
        float e = al[s_c] + arn;
        e_c = (e >= 0.f) ? e : LRELU_S * e;
        m = e_c;
        ss = 1.f;
    }
    for (int i = start + lane + 32; i < end; i += 32) {
        int s = csr[i];
        float e = al[s] + arn;
        e = (e >= 0.f) ? e : LRELU_S * e;
        if (e > m) {
            ss = ss * __expf(m - e) + 1.f;
            m = e;
        } else {
            ss += __expf(e - m);
        }
    }
#pragma unroll
    for (int o = 16; o; o >>= 1) {
        float mo = __shfl_xor_sync(FULL, m, o);
        float so = __shfl_xor_sync(FULL, ss, o);
        float M = fmaxf(m, mo);
        ss = ss * __expf(m - M) + so * __expf(mo - M);
        m = M;
    }

    // stage weights + fp16 rows (64B each = 4 x 16B chunks)
    sp[wid][lane] = (lane < deg) ? __expf(e_c - m) : 0.f;
    int cnt = (deg < 32) ? deg : 32;
    int r = lane >> 2;           // row octet 0..7
    int c = (lane & 3) * 8;      // 16B chunk within row (in halfs)
#pragma unroll
    for (int j = 0; j < 4; j++) {
        int row = j * 8 + r;
        int s = __shfl_sync(FULL, s_c, row);
        if (row < cnt) cp_async16(&svh[wid][row][c], &hh[s * HD + c]);
    }
    cp_commit();
    cp_wait0();
    __syncwarp();

    // consume
    float acc = 0.f;
    for (int k = 0; k < cnt; k++) {
        acc += sp[wid][k] * __half2float(svh[wid][k][lane]);
    }
    // rare slow path: degree > 32
    for (int i = start + 32; i < end; i++) {
        int s = csr[i];
        float e = al[s] + arn;
        e = (e >= 0.f) ? e : LRELU_S * e;
        acc += __expf(e - m) * __half2float(hh[s * HD + lane]);
    }
    float res = acc / (ss + 1e-16f) + bias[lane];
    res = (res >= 0.f) ? res : PRELU_S * res;
    out[node * HD + lane] = res;
    if (write_cc) g_cc[node][graph * HD + lane] = __float2half(res);
}

// ---------------- inner node transform: c = se + sk; h = c @ W; al/ar dots ----------------
__global__ void k_transform(const float* __restrict__ Ws, const float* __restrict__ a1s, const float* __restrict__ a2s,
                            const float* __restrict__ Wk, const float* __restrict__ a1k, const float* __restrict__ a2k) {
    __shared__ float sWs[HD * HD];
    __shared__ float sWk[HD * HD];
    for (int i = threadIdx.x; i < HD * HD; i += blockDim.x) {
        sWs[i] = Ws[i];
        sWk[i] = Wk[i];
    }
    __syncthreads();
    int lane = threadIdx.x & 31;
    int n = (blockIdx.x * blockDim.x + threadIdx.x) >> 5;
    if (n >= NN) return;
    float va1s = a1s[lane], va2s = a2s[lane], va1k = a1k[lane], va2k = a2k[lane];
    float cj = g_se[n * HD + lane] + g_sk[n * HD + lane];
    float accS = 0.f, accK = 0.f;
#pragma unroll
    for (int k = 0; k < HD; k++) {
        float ck = __shfl_sync(FULL, cj, k);
        accS += ck * sWs[k * HD + lane];
        accK += ck * sWk[k * HD + lane];
    }
    g_hh[0][n * HD + lane] = __float2half(accS);
    g_hh[1][n * HD + lane] = __float2half(accK);
    float r0 = accS * va1s, r1 = accS * va2s, r2 = accK * va1k, r3 = accK * va2k;
#pragma unroll
    for (int o = 16; o; o >>= 1) {
        r0 += __shfl_xor_sync(FULL, r0, o);
        r1 += __shfl_xor_sync(FULL, r1, o);
        r2 += __shfl_xor_sync(FULL, r2, o);
        r3 += __shfl_xor_sync(FULL, r3, o);
    }
    if (lane == 0) {
        g_al[0][n] = r0;
        g_ar[0][n] = r1;
        g_al[1][n] = r2;
        g_ar[1][n] = r3;
    }
}

// ---------------- final head: one packed 128B row per edge ----------------
__global__ void __launch_bounds__(256) k_final(const float* __restrict__ x,
                        const float* __restrict__ Wos, const float* __restrict__ bos,
                        const float* __restrict__ Wok, const float* __restrict__ bok,
                        const float* __restrict__ Wd1, const float* __restrict__ bd1,
                        float* __restrict__ out) {
    __shared__ __half svh[8][32][2 * HD];   // 32KB: packed [se|sk] rows
    __shared__ float  sp[8][32];
    int wid = threadIdx.x >> 5;
    int lane = threadIdx.x & 31;
    int w = (blockIdx.x * blockDim.x + threadIdx.x) >> 5;
    if (w >= NN) return;

    float c0 = g_se[w * HD + lane];
    float c1 = g_sk[w * HD + lane];

    // final_dim0 dots
    float d00 = c0 * Wos[lane * 2]     + c1 * Wos[(HD + lane) * 2];
    float d01 = c0 * Wos[lane * 2 + 1] + c1 * Wos[(HD + lane) * 2 + 1];
    float d10 = c0 * Wok[lane * 2]     + c1 * Wok[(HD + lane) * 2];
    float d11 = c0 * Wok[lane * 2 + 1] + c1 * Wok[(HD + lane) * 2 + 1];
#pragma unroll
    for (int o = 16; o; o >>= 1) {
        d00 += __shfl_xor_sync(FULL, d00, o);
        d01 += __shfl_xor_sync(FULL, d01, o);
        d10 += __shfl_xor_sync(FULL, d10, o);
        d11 += __shfl_xor_sync(FULL, d11, o);
    }

    int r = lane >> 3;           // row quarter 0..3
    int c = (lane & 7) * 8;      // 16B chunk within 128B row (in halfs)

    float aggS[2], aggK[2];      // per graph
#pragma unroll
    for (int g = 0; g < 2; g++) {
        const int* __restrict__ csr = g_csr[g];
        int st = g_rowptr[g][w], en = g_rowptr[g][w + 1];
        int deg = en - st;
        int cnt = (deg < 32) ? deg : 32;
        int s_c = 0; float x_c = 0.f;
        if (lane < deg) { s_c = csr[st + lane]; x_c = x[s_c]; }
        sp[wid][lane] = x_c;

        // stage packed [se|sk] rows (128B each = 8 x 16B chunks)
#pragma unroll
        for (int j = 0; j < 8; j++) {
            int row = j * 4 + r;
            int s = __shfl_sync(FULL, s_c, row);
            if (row < cnt) cp_async16(&svh[wid][row][c], &g_cc[s][c]);
        }
        cp_commit();
        cp_wait0();
        __syncwarp();
        float a0 = 0.f, a1v = 0.f;
        for (int k = 0; k < cnt; k++) {
            float xs = sp[wid][k];
            a0  += xs * __half2float(svh[wid][k][lane]);
            a1v += xs * __half2float(svh[wid][k][HD + lane]);
        }
        __syncwarp();

        // slow path: degree > 32
        for (int i = st + 32; i < en; i++) {
            int s = csr[i];
            float xs = x[s];
            a0  += xs * __half2float(g_cc[s][lane]);
            a1v += xs * __half2float(g_cc[s][HD + lane]);
        }
        aggS[g] = a0;
        aggK[g] = a1v;
    }

    float e1s0 = aggS[0] + 0.5f * c0;  e1s0 = (e1s0 > 0.f) ? e1s0 : 0.f;
    float e1s1 = aggK[0] + 0.5f * c1;  e1s1 = (e1s1 > 0.f) ? e1s1 : 0.f;
    float e1k0 = aggS[1] + 0.5f * c0;  e1k0 = (e1k0 > 0.f) ? e1k0 : 0.f;
    float e1k1 = aggK[1] + 0.5f * c1;  e1k1 = (e1k1 > 0.f) ? e1k1 : 0.f;

    float t0 = e1s0 + e1k0;
    float t1 = e1s1 + e1k1;
    float g0 = t0 * Wd1[lane * 2]     + t1 * Wd1[(HD + lane) * 2];
    float g1 = t0 * Wd1[lane * 2 + 1] + t1 * Wd1[(HD + lane) * 2 + 1];
#pragma unroll
    for (int o = 16; o; o >>= 1) {
        g0 += __shfl_xor_sync(FULL, g0, o);
        g1 += __shfl_xor_sync(FULL, g1, o);
    }

    if (lane == 0) {
        float s0 = d00 + bos[0]; s0 = (s0 > 0.f) ? s0 : 0.f;
        float s1 = d01 + bos[1]; s1 = (s1 > 0.f) ? s1 : 0.f;
        float k0 = d10 + bok[0]; k0 = (k0 > 0.f) ? k0 : 0.f;
        float k1 = d11 + bok[1]; k1 = (k1 > 0.f) ? k1 : 0.f;
        out[w * 4 + 0] = 0.5f * (s0 + k0);
        out[w * 4 + 1] = 0.5f * (s1 + k1);
        float f2 = g0 + bd1[0];
        float f3 = g1 + bd1[1];
        out[w * 4 + 2] = (f2 > 0.f) ? f2 : 0.f;
        out[w * 4 + 3] = (f3 > 0.f) ? f3 : 0.f;
    }
}

// ---------------- launch ----------------
extern "C" void kernel_launch(void* const* d_in, const int* in_sizes, int n_in,
                              void* d_out, int out_size) {
    const float* x        = (const float*)d_in[0];
    const int*   sei      = (const int*)d_in[1];
    const int*   kei      = (const int*)d_in[2];
    const float* W_in_src = (const float*)d_in[3];
    const float* b_in_src = (const float*)d_in[4];
    const float* a1_in_src= (const float*)d_in[5];
    const float* a2_in_src= (const float*)d_in[6];
    const float* W_in_snk = (const float*)d_in[7];
    const float* b_in_snk = (const float*)d_in[8];
    const float* a1_in_snk= (const float*)d_in[9];
    const float* a2_in_snk= (const float*)d_in[10];
    const float* W_src    = (const float*)d_in[11];
    const float* b_src    = (const float*)d_in[12];
    const float* a1_src   = (const float*)d_in[13];
    const float* a2_src   = (const float*)d_in[14];
    const float* W_snk    = (const float*)d_in[15];
    const float* b_snk    = (const float*)d_in[16];
    const float* a1_snk   = (const float*)d_in[17];
    const float* a2_snk   = (const float*)d_in[18];
    const float* W_o_src  = (const float*)d_in[19];
    const float* b_o_src  = (const float*)d_in[20];
    const float* W_o_snk  = (const float*)d_in[21];
    const float* b_o_snk  = (const float*)d_in[22];
    const float* W_d1     = (const float*)d_in[23];
    const float* b_d1     = (const float*)d_in[24];
    float* out = (float*)d_out;

    const int* s0 = sei;
    const int* dd0 = sei + EE;
    const int* s1 = kei;
    const int* dd1 = kei + EE;

    const int TB = 256;

    k_zero_deg<<<(2 * NN + TB - 1) / TB, TB>>>();
    k_degree<<<(EE + TB - 1) / TB, TB>>>(dd0, dd1);
    {
        dim3 g(SCAN_NB, 2);
        k_scan1<<<g, 512>>>();
    }
    {
        dim3 g((NN + TB - 1) / TB, 2);
        k_scan3<<<g, TB>>>();
    }
    k_fill_t0<<<FILL_BLOCKS + T0_BLOCKS, TB>>>(s0, dd0, s1, dd1, x,
                                               W_in_src, a1_in_src, a2_in_src,
                                               W_in_snk, a1_in_snk, a2_in_snk);

    int agg_blocks = (2 * NN * 32 + TB - 1) / TB;
    int node_blocks = (NN * 32 + TB - 1) / TB;

    k_gat_agg<<<agg_blocks, TB>>>(b_in_src, b_in_snk, 0);

    for (int i = 0; i < 4; i++) {
        k_transform<<<node_blocks, TB>>>(W_src + i * HD * HD, a1_src + i * HD, a2_src + i * HD,
                                         W_snk + i * HD * HD, a1_snk + i * HD, a2_snk + i * HD);
        k_gat_agg<<<agg_blocks, TB>>>(b_src + i * HD, b_snk + i * HD, i == 3);
    }

    k_final<<<node_blocks, TB>>>(x, W_o_src, b_o_src, W_o_snk, b_o_snk, W_d1, b_d1, out);
}

// round 6
// speedup vs baseline: 1.3214x; 1.0109x over previous
#include <cuda_runtime.h>
#include <cuda_fp16.h>

#define NN 100000
#define EE 1600000
#define HD 32
#define LRELU_S 0.2f
#define PRELU_S 0.1f
#define FULL 0xffffffffu

// ---------------- cp.async helpers ----------------
__device__ __forceinline__ void cp_async16(void* smem_dst, const void* gmem_src) {
    unsigned sa = (unsigned)__cvta_generic_to_shared(smem_dst);
    asm volatile("cp.async.cg.shared.global [%0], [%1], 16;\n" :: "r"(sa), "l"(gmem_src) : "memory");
}
__device__ __forceinline__ void cp_commit() { asm volatile("cp.async.commit_group;\n" ::: "memory"); }
__device__ __forceinline__ void cp_wait0()  { asm volatile("cp.async.wait_group 0;\n" ::: "memory"); }

// ---------------- static device scratch (no allocations allowed) ----------------
__device__ int    g_deg[2][NN];                 // zero-initialized; re-zeroed each call in k_fill_t0
__device__ int    g_rowptr[2][NN + 1];
__device__ int    g_cursor[2][NN];
__device__ int    g_csr[2][EE];
__device__ __align__(128) __half g_hh[2][NN * HD];   // fp16 message values
__device__ float  g_al[2][NN];
__device__ float  g_ar[2][NN];
__device__ __align__(128) float g_se[NN * HD];
__device__ __align__(128) float g_sk[NN * HD];
__device__ __align__(128) __half g_cc[NN][2 * HD];   // packed fp16 x*[se|sk] for final head
__device__ int    g_part[2][32];

#define SCAN_NB ((NN + 4095) / 4096)

// ---------------- launch 1: degree histogram (both graphs) ----------------
__global__ void k_degree(const int* __restrict__ d0, const int* __restrict__ d1) {
    int i = blockIdx.x * blockDim.x + threadIdx.x;
    if (i < EE) {
        atomicAdd(&g_deg[0][d0[i]], 1);
        atomicAdd(&g_deg[1][d1[i]], 1);
    }
}

// ---------------- launch 2: per-tile exclusive scan, both graphs ----------------
__global__ void k_scan1(void) {
    __shared__ int sh[512];
    int graph = blockIdx.y;
    const int* deg = g_deg[graph];
    int* out = g_rowptr[graph];
    int base = blockIdx.x * 4096;
    int tid = threadIdx.x;
    int v[8];
    int s = 0;
#pragma unroll
    for (int k = 0; k < 8; k++) {
        int idx = base + tid * 8 + k;
        v[k] = (idx < NN) ? deg[idx] : 0;
        s += v[k];
    }
    sh[tid] = s;
    __syncthreads();
    for (int off = 1; off < 512; off <<= 1) {
        int t = (tid >= off) ? sh[tid - off] : 0;
        __syncthreads();
        sh[tid] += t;
        __syncthreads();
    }
    if (tid == 511) g_part[graph][blockIdx.x] = sh[511];
    int run = (tid > 0) ? sh[tid - 1] : 0;
#pragma unroll
    for (int k = 0; k < 8; k++) {
        int idx = base + tid * 8 + k;
        if (idx < NN) out[idx] = run;
        run += v[k];
    }
}

// ---------------- launch 3: add tile offsets, both graphs ----------------
__global__ void k_scan3(void) {
    __shared__ int sPre[32];
    int graph = blockIdx.y;
    if (threadIdx.x < 32) {
        int lane = threadIdx.x;
        int v = (lane < SCAN_NB) ? g_part[graph][lane] : 0;
        int inc = v;
#pragma unroll
        for (int o = 1; o < 32; o <<= 1) {
            int t = __shfl_up_sync(FULL, inc, o);
            if (lane >= o) inc += t;
        }
        sPre[lane] = inc - v;
    }
    __syncthreads();
    int i = blockIdx.x * blockDim.x + threadIdx.x;
    if (i < NN) {
        int v = g_rowptr[graph][i] + sPre[i >> 12];
        g_rowptr[graph][i] = v;
        g_cursor[graph][i] = v;
    }
    if (i == 0) g_rowptr[graph][NN] = EE;
}

// ---------------- launch 4: CSR fill (both graphs) + deg re-zero + layer-0 transform ----------------
#define FILL_BLOCKS ((EE + 255) / 256)
#define T0_BLOCKS   ((NN * 32 + 255) / 256)

__global__ void k_fill_t0(const int* __restrict__ s0, const int* __restrict__ d0,
                          const int* __restrict__ s1, const int* __restrict__ d1,
                          const float* __restrict__ x,
                          const float* __restrict__ Ws, const float* __restrict__ a1s, const float* __restrict__ a2s,
                          const float* __restrict__ Wk, const float* __restrict__ a1k, const float* __restrict__ a2k) {
    if (blockIdx.x < FILL_BLOCKS) {
        int i = blockIdx.x * blockDim.x + threadIdx.x;
        if (i < EE) {
            {
                int d = d0[i];
                int p = atomicAdd(&g_cursor[0][d], 1);
                g_csr[0][p] = s0[i];
            }
            {
                int d = d1[i];
                int p = atomicAdd(&g_cursor[1][d], 1);
                g_csr[1][p] = s1[i];
            }
        }
        return;
    }
    int gtid = (blockIdx.x - FILL_BLOCKS) * blockDim.x + threadIdx.x;
    int w = gtid >> 5;
    int lane = threadIdx.x & 31;
    if (w >= NN) return;
    if (lane < 2) g_deg[lane][w] = 0;     // re-zero for next call (scan already consumed)
    float xv = x[w];
    float hs = xv * Ws[lane];
    float hk = xv * Wk[lane];
    g_hh[0][w * HD + lane] = __float2half(hs);
    g_hh[1][w * HD + lane] = __float2half(hk);
    float r0 = hs * a1s[lane], r1 = hs * a2s[lane];
    float r2 = hk * a1k[lane], r3 = hk * a2k[lane];
#pragma unroll
    for (int o = 16; o; o >>= 1) {
        r0 += __shfl_xor_sync(FULL, r0, o);
        r1 += __shfl_xor_sync(FULL, r1, o);
        r2 += __shfl_xor_sync(FULL, r2, o);
        r3 += __shfl_xor_sync(FULL, r3, o);
    }
    if (lane == 0) {
        g_al[0][w] = r0;
        g_ar[0][w] = r1;
        g_al[1][w] = r2;
        g_ar[1][w] = r3;
    }
}

// ---------------- GAT aggregation: early cp.async staging + half2 consume ----------------
// write_cc: also emit packed fp16 x*[se|sk] rows (only for last layer)
__global__ void __launch_bounds__(256) k_gat_agg(const float* __restrict__ bias0,
                                                 const float* __restrict__ bias1,
                                                 const float* __restrict__ x,
                                                 int write_cc) {
    __shared__ __half svh[8][32][HD];   // 16KB: staged fp16 h rows per warp
    int wid = threadIdx.x >> 5;
    int lane = threadIdx.x & 31;
    int w = (blockIdx.x * blockDim.x + threadIdx.x) >> 5;
    if (w >= 2 * NN) return;
    int graph = (w >= NN);
    int node = w - graph * NN;
    const int* __restrict__ rp = g_rowptr[graph];
    const int* __restrict__ csr = g_csr[graph];
    const float* __restrict__ al = g_al[graph];
    const __half* __restrict__ hh = g_hh[graph];
    const float* __restrict__ bias = graph ? bias1 : bias0;
    float* __restrict__ out = graph ? g_sk : g_se;

    int start = rp[node], end = rp[node + 1];
    int deg = end - start;
    float arn = g_ar[graph][node];

    int s_c = 0;
    if (lane < deg) s_c = csr[start + lane];
    int cnt = (deg < 32) ? deg : 32;

    // early staging: rows don't depend on softmax weights
    {
        int r = lane >> 2;           // row octet 0..7
        int c = (lane & 3) * 8;      // 16B chunk within 64B row (in halfs)
#pragma unroll
        for (int j = 0; j < 4; j++) {
            int row = j * 8 + r;
            int s = __shfl_sync(FULL, s_c, row);
            if (row < cnt) cp_async16(&svh[wid][row][c], &hh[s * HD + c]);
        }
        cp_commit();
    }

    // pass 1: online (max, sum-exp)
    float e_c = -1e30f;
    float m = -1e30f, ss = 0.f;
    if (lane < deg) {
        float e = al[s_c] + arn;
        e_c = (e >= 0.f) ? e : LRELU_S * e;
        m = e_c;
        ss = 1.f;
    }
    for (int i = start + lane + 32; i < end; i += 32) {
        int s = csr[i];
        float e = al[s] + arn;
        e = (e >= 0.f) ? e : LRELU_S * e;
        if (e > m) {
            ss = ss * __expf(m - e) + 1.f;
            m = e;
        } else {
            ss += __expf(e - m);
        }
    }
#pragma unroll
    for (int o = 16; o; o >>= 1) {
        float mo = __shfl_xor_sync(FULL, m, o);
        float so = __shfl_xor_sync(FULL, ss, o);
        float M = fmaxf(m, mo);
        ss = ss * __expf(m - M) + so * __expf(mo - M);
        m = M;
    }
    float p_c = __expf(e_c - m);   // 0 for invalid lanes

    cp_wait0();
    __syncwarp();

    // consume: half2, half-warps split rows
    int hw = lane >> 4;
    int p = lane & 15;
    float2 acc = make_float2(0.f, 0.f);
    for (int k = 0; k < cnt; k += 2) {
        int row = k + hw;
        float wgt = __shfl_sync(FULL, p_c, row & 31);
        if (row < cnt) {
            __half2 v = *(const __half2*)&svh[wid][row][2 * p];
            float2 f = __half22float2(v);
            acc.x += wgt * f.x;
            acc.y += wgt * f.y;
        }
    }
    // rare slow path: degree > 32 (half-warps alternate edges)
    for (int i = start + 32 + hw; i < end; i += 2) {
        int s = csr[i];
        float e = al[s] + arn;
        e = (e >= 0.f) ? e : LRELU_S * e;
        float pw = __expf(e - m);
        __half2 v = *(const __half2*)&hh[s * HD + 2 * p];
        float2 f = __half22float2(v);
        acc.x += pw * f.x;
        acc.y += pw * f.y;
    }
    // combine half-warps
    acc.x += __shfl_xor_sync(FULL, acc.x, 16);
    acc.y += __shfl_xor_sync(FULL, acc.y, 16);

    float inv = 1.f / (ss + 1e-16f);
    float2 b2 = *(const float2*)&bias[2 * p];
    float r0 = acc.x * inv + b2.x; r0 = (r0 >= 0.f) ? r0 : PRELU_S * r0;
    float r1 = acc.y * inv + b2.y; r1 = (r1 >= 0.f) ? r1 : PRELU_S * r1;
    if (lane < 16) {
        *(float2*)&out[node * HD + 2 * p] = make_float2(r0, r1);
        if (write_cc) {
            float xv = x[node];
            *(__half2*)&g_cc[node][graph * HD + 2 * p] = __floats2half2_rn(r0 * xv, r1 * xv);
        }
    }
}

// ---------------- inner node transform: c = se + sk; h = c @ W; al/ar dots ----------------
__global__ void k_transform(const float* __restrict__ Ws, const float* __restrict__ a1s, const float* __restrict__ a2s,
                            const float* __restrict__ Wk, const float* __restrict__ a1k, const float* __restrict__ a2k) {
    __shared__ float sWs[HD * HD];
    __shared__ float sWk[HD * HD];
    for (int i = threadIdx.x; i < HD * HD; i += blockDim.x) {
        sWs[i] = Ws[i];
        sWk[i] = Wk[i];
    }
    __syncthreads();
    int lane = threadIdx.x & 31;
    int n = (blockIdx.x * blockDim.x + threadIdx.x) >> 5;
    if (n >= NN) return;
    float va1s = a1s[lane], va2s = a2s[lane], va1k = a1k[lane], va2k = a2k[lane];
    float cj = g_se[n * HD + lane] + g_sk[n * HD + lane];
    float accS = 0.f, accK = 0.f;
#pragma unroll
    for (int k = 0; k < HD; k++) {
        float ck = __shfl_sync(FULL, cj, k);
        accS += ck * sWs[k * HD + lane];
        accK += ck * sWk[k * HD + lane];
    }
    g_hh[0][n * HD + lane] = __float2half(accS);
    g_hh[1][n * HD + lane] = __float2half(accK);
    float r0 = accS * va1s, r1 = accS * va2s, r2 = accK * va1k, r3 = accK * va2k;
#pragma unroll
    for (int o = 16; o; o >>= 1) {
        r0 += __shfl_xor_sync(FULL, r0, o);
        r1 += __shfl_xor_sync(FULL, r1, o);
        r2 += __shfl_xor_sync(FULL, r2, o);
        r3 += __shfl_xor_sync(FULL, r3, o);
    }
    if (lane == 0) {
        g_al[0][n] = r0;
        g_ar[0][n] = r1;
        g_al[1][n] = r2;
        g_ar[1][n] = r3;
    }
}

// ---------------- final head: premultiplied cc rows, unweighted sum ----------------
// lane l owns comb columns (2l, 2l+1) of the 64-dim comb vector
__global__ void __launch_bounds__(256) k_final(
                        const float* __restrict__ Wos, const float* __restrict__ bos,
                        const float* __restrict__ Wok, const float* __restrict__ bok,
                        const float* __restrict__ Wd1, const float* __restrict__ bd1,
                        float* __restrict__ out) {
    __shared__ __half svh[8][32][2 * HD];   // 32KB: packed cc rows
    int wid = threadIdx.x >> 5;
    int lane = threadIdx.x & 31;
    int w = (blockIdx.x * blockDim.x + threadIdx.x) >> 5;
    if (w >= NN) return;

    // comb cols (2l, 2l+1)
    float2 c2;
    if (lane < 16) c2 = *(const float2*)&g_se[w * HD + 2 * lane];
    else           c2 = *(const float2*)&g_sk[w * HD + 2 * (lane - 16)];

    // final_dim0 dots (Wos/Wok are [64][2] row-major; float4 covers both cols of both rows)
    float4 wos = *(const float4*)&Wos[4 * lane];
    float4 wok = *(const float4*)&Wok[4 * lane];
    float d00 = c2.x * wos.x + c2.y * wos.z;
    float d01 = c2.x * wos.y + c2.y * wos.w;
    float d10 = c2.x * wok.x + c2.y * wok.z;
    float d11 = c2.x * wok.y + c2.y * wok.w;
#pragma unroll
    for (int o = 16; o; o >>= 1) {
        d00 += __shfl_xor_sync(FULL, d00, o);
        d01 += __shfl_xor_sync(FULL, d01, o);
        d10 += __shfl_xor_sync(FULL, d10, o);
        d11 += __shfl_xor_sync(FULL, d11, o);
    }

    float2 agg[2];
#pragma unroll
    for (int g = 0; g < 2; g++) {
        const int* __restrict__ csr = g_csr[g];
        int st = g_rowptr[g][w], en = g_rowptr[g][w + 1];
        int deg = en - st;
        int cnt = (deg < 32) ? deg : 32;
        int s_c = 0;
        if (lane < deg) s_c = csr[st + lane];

        // stage packed cc rows (128B = 8 x 16B chunks)
        int r = lane >> 3;
        int c = (lane & 7) * 8;
#pragma unroll
        for (int j = 0; j < 8; j++) {
            int row = j * 4 + r;
            int s = __shfl_sync(FULL, s_c, row);
            if (row < cnt) cp_async16(&svh[wid][row][c], &g_cc[s][c]);
        }
        cp_commit();
        cp_wait0();
        __syncwarp();

        float2 a = make_float2(0.f, 0.f);
        for (int k = 0; k < cnt; k++) {
            __half2 v = *(const __half2*)&svh[wid][k][2 * lane];
            float2 f = __half22float2(v);
            a.x += f.x;
            a.y += f.y;
        }
        // slow path: degree > 32 (uniform row load per edge)
        for (int i = st + 32; i < en; i++) {
            int s = csr[i];
            __half2 v = *(const __half2*)&g_cc[s][2 * lane];
            float2 f = __half22float2(v);
            a.x += f.x;
            a.y += f.y;
        }
        agg[g] = a;
        __syncwarp();
    }

    float e1sx = agg[0].x + 0.5f * c2.x; e1sx = (e1sx > 0.f) ? e1sx : 0.f;
    float e1sy = agg[0].y + 0.5f * c2.y; e1sy = (e1sy > 0.f) ? e1sy : 0.f;
    float e1kx = agg[1].x + 0.5f * c2.x; e1kx = (e1kx > 0.f) ? e1kx : 0.f;
    float e1ky = agg[1].y + 0.5f * c2.y; e1ky = (e1ky > 0.f) ? e1ky : 0.f;

    float tx = e1sx + e1kx;
    float ty = e1sy + e1ky;
    float4 wd = *(const float4*)&Wd1[4 * lane];
    float g0 = tx * wd.x + ty * wd.z;
    float g1 = tx * wd.y + ty * wd.w;
#pragma unroll
    for (int o = 16; o; o >>= 1) {
        g0 += __shfl_xor_sync(FULL, g0, o);
        g1 += __shfl_xor_sync(FULL, g1, o);
    }

    if (lane == 0) {
        float s0 = d00 + bos[0]; s0 = (s0 > 0.f) ? s0 : 0.f;
        float s1 = d01 + bos[1]; s1 = (s1 > 0.f) ? s1 : 0.f;
        float k0 = d10 + bok[0]; k0 = (k0 > 0.f) ? k0 : 0.f;
        float k1 = d11 + bok[1]; k1 = (k1 > 0.f) ? k1 : 0.f;
        out[w * 4 + 0] = 0.5f * (s0 + k0);
        out[w * 4 + 1] = 0.5f * (s1 + k1);
        float f2 = g0 + bd1[0];
        float f3 = g1 + bd1[1];
        out[w * 4 + 2] = (f2 > 0.f) ? f2 : 0.f;
        out[w * 4 + 3] = (f3 > 0.f) ? f3 : 0.f;
    }
}

// ---------------- launch ----------------
extern "C" void kernel_launch(void* const* d_in, const int* in_sizes, int n_in,
                              void* d_out, int out_size) {
    const float* x        = (const float*)d_in[0];
    const int*   sei      = (const int*)d_in[1];
    const int*   kei      = (const int*)d_in[2];
    const float* W_in_src = (const float*)d_in[3];
    const float* b_in_src = (const float*)d_in[4];
    const float* a1_in_src= (const float*)d_in[5];
    const float* a2_in_src= (const float*)d_in[6];
    const float* W_in_snk = (const float*)d_in[7];
    const float* b_in_snk = (const float*)d_in[8];
    const float* a1_in_snk= (const float*)d_in[9];
    const float* a2_in_snk= (const float*)d_in[10];
    const float* W_src    = (const float*)d_in[11];
    const float* b_src    = (const float*)d_in[12];
    const float* a1_src   = (const float*)d_in[13];
    const float* a2_src   = (const float*)d_in[14];
    const float* W_snk    = (const float*)d_in[15];
    const float* b_snk    = (const float*)d_in[16];
    const float* a1_snk   = (const float*)d_in[17];
    const float* a2_snk   = (const float*)d_in[18];
    const float* W_o_src  = (const float*)d_in[19];
    const float* b_o_src  = (const float*)d_in[20];
    const float* W_o_snk  = (const float*)d_in[21];
    const float* b_o_snk  = (const float*)d_in[22];
    const float* W_d1     = (const float*)d_in[23];
    const float* b_d1     = (const float*)d_in[24];
    float* out = (float*)d_out;

    const int* s0 = sei;
    const int* dd0 = sei + EE;
    const int* s1 = kei;
    const int* dd1 = kei + EE;

    const int TB = 256;

    k_degree<<<(EE + TB - 1) / TB, TB>>>(dd0, dd1);
    {
        dim3 g(SCAN_NB, 2);
        k_scan1<<<g, 512>>>();
    }
    {
        dim3 g((NN + TB - 1) / TB, 2);
        k_scan3<<<g, TB>>>();
    }
    k_fill_t0<<<FILL_BLOCKS + T0_BLOCKS, TB>>>(s0, dd0, s1, dd1, x,
                                               W_in_src, a1_in_src, a2_in_src,
                                               W_in_snk, a1_in_snk, a2_in_snk);

    int agg_blocks = (2 * NN * 32 + TB - 1) / TB;
    int node_blocks = (NN * 32 + TB - 1) / TB;

    k_gat_agg<<<agg_blocks, TB>>>(b_in_src, b_in_snk, x, 0);

    for (int i = 0; i < 4; i++) {
        k_transform<<<node_blocks, TB>>>(W_src + i * HD * HD, a1_src + i * HD, a2_src + i * HD,
                                         W_snk + i * HD * HD, a1_snk + i * HD, a2_snk + i * HD);
        k_gat_agg<<<agg_blocks, TB>>>(b_src + i * HD, b_snk + i * HD, x, i == 3);
    }

    k_final<<<node_blocks, TB>>>(W_o_src, b_o_src, W_o_snk, b_o_snk, W_d1, b_d1, out);
}

// round 7
// speedup vs baseline: 1.4758x; 1.1168x over previous
#include <cuda_runtime.h>
#include <cuda_fp16.h>

#define NN 100000
#define EE 1600000
#define HD 32
#define LRELU_S 0.2f
#define PRELU_S 0.1f
#define FULL 0xffffffffu

// ---------------- cp.async helpers ----------------
__device__ __forceinline__ void cp_async16(void* smem_dst, const void* gmem_src) {
    unsigned sa = (unsigned)__cvta_generic_to_shared(smem_dst);
    asm volatile("cp.async.cg.shared.global [%0], [%1], 16;\n" :: "r"(sa), "l"(gmem_src) : "memory");
}
__device__ __forceinline__ void cp_commit() { asm volatile("cp.async.commit_group;\n" ::: "memory"); }
__device__ __forceinline__ void cp_wait0()  { asm volatile("cp.async.wait_group 0;\n" ::: "memory"); }

// ---------------- static device scratch ----------------
__device__ int    g_deg[2][NN];                 // zero-init; re-zeroed each call in k_fill_t0
__device__ int    g_rank[2][EE];                // edge rank within dst segment
__device__ int    g_rowptr[2][NN + 1];
__device__ int    g_csr[2][EE];
__device__ __align__(128) __half g_hh[2][2][NN * HD];   // [buf][graph] fp16 messages
__device__ float  g_al[2][2][NN];
__device__ float  g_ar[2][2][NN];
__device__ __align__(128) float g_se[NN * HD];
__device__ __align__(128) float g_sk[NN * HD];
__device__ __align__(128) __half g_cc[NN][2 * HD];      // fp16 x*[se|sk] for final head
__device__ int    g_part[2][32];

#define SCAN_NB ((NN + 4095) / 4096)

// ---------------- launch 1: degree histogram + edge rank (both graphs) ----------------
__global__ void k_degree(const int* __restrict__ d0, const int* __restrict__ d1) {
    int i = blockIdx.x * blockDim.x + threadIdx.x;
    if (i < EE) {
        g_rank[0][i] = atomicAdd(&g_deg[0][d0[i]], 1);
        g_rank[1][i] = atomicAdd(&g_deg[1][d1[i]], 1);
    }
}

// ---------------- launch 2: per-tile exclusive scan, both graphs ----------------
__global__ void k_scan1(void) {
    __shared__ int sh[512];
    int graph = blockIdx.y;
    const int* deg = g_deg[graph];
    int* out = g_rowptr[graph];
    int base = blockIdx.x * 4096;
    int tid = threadIdx.x;
    int v[8];
    int s = 0;
#pragma unroll
    for (int k = 0; k < 8; k++) {
        int idx = base + tid * 8 + k;
        v[k] = (idx < NN) ? deg[idx] : 0;
        s += v[k];
    }
    sh[tid] = s;
    __syncthreads();
    for (int off = 1; off < 512; off <<= 1) {
        int t = (tid >= off) ? sh[tid - off] : 0;
        __syncthreads();
        sh[tid] += t;
        __syncthreads();
    }
    if (tid == 511) g_part[graph][blockIdx.x] = sh[511];
    int run = (tid > 0) ? sh[tid - 1] : 0;
#pragma unroll
    for (int k = 0; k < 8; k++) {
        int idx = base + tid * 8 + k;
        if (idx < NN) out[idx] = run;
        run += v[k];
    }
}

// ---------------- launch 3: add tile offsets, both graphs ----------------
__global__ void k_scan3(void) {
    __shared__ int sPre[32];
    int graph = blockIdx.y;
    if (threadIdx.x < 32) {
        int lane = threadIdx.x;
        int v = (lane < SCAN_NB) ? g_part[graph][lane] : 0;
        int inc = v;
#pragma unroll
        for (int o = 1; o < 32; o <<= 1) {
            int t = __shfl_up_sync(FULL, inc, o);
            if (lane >= o) inc += t;
        }
        sPre[lane] = inc - v;
    }
    __syncthreads();
    int i = blockIdx.x * blockDim.x + threadIdx.x;
    if (i < NN) g_rowptr[graph][i] += sPre[i >> 12];
    if (i == 0) g_rowptr[graph][NN] = EE;
}

// ---------------- launch 4: atomic-free CSR fill + deg re-zero + layer-0 transform ----------------
#define FILL_BLOCKS ((EE + 255) / 256)
#define T0_BLOCKS   ((NN * 32 + 255) / 256)

__global__ void k_fill_t0(const int* __restrict__ s0, const int* __restrict__ d0,
                          const int* __restrict__ s1, const int* __restrict__ d1,
                          const float* __restrict__ x,
                          const float* __restrict__ Ws, const float* __restrict__ a1s, const float* __restrict__ a2s,
                          const float* __restrict__ Wk, const float* __restrict__ a1k, const float* __restrict__ a2k) {
    if (blockIdx.x < FILL_BLOCKS) {
        int i = blockIdx.x * blockDim.x + threadIdx.x;
        if (i < EE) {
            {
                int d = d0[i];
                g_csr[0][g_rowptr[0][d] + g_rank[0][i]] = s0[i];
            }
            {
                int d = d1[i];
                g_csr[1][g_rowptr[1][d] + g_rank[1][i]] = s1[i];
            }
        }
        return;
    }
    int gtid = (blockIdx.x - FILL_BLOCKS) * blockDim.x + threadIdx.x;
    int w = gtid >> 5;
    int lane = threadIdx.x & 31;
    if (w >= NN) return;
    if (lane < 2) g_deg[lane][w] = 0;     // re-zero for next call (scan already consumed)
    float xv = x[w];
    float hs = xv * Ws[lane];
    float hk = xv * Wk[lane];
    g_hh[0][0][w * HD + lane] = __float2half(hs);
    g_hh[0][1][w * HD + lane] = __float2half(hk);
    float r0 = hs * a1s[lane], r1 = hs * a2s[lane];
    float r2 = hk * a1k[lane], r3 = hk * a2k[lane];
#pragma unroll
    for (int o = 16; o; o >>= 1) {
        r0 += __shfl_xor_sync(FULL, r0, o);
        r1 += __shfl_xor_sync(FULL, r1, o);
        r2 += __shfl_xor_sync(FULL, r2, o);
        r3 += __shfl_xor_sync(FULL, r3, o);
    }
    if (lane == 0) {
        g_al[0][0][w] = r0;
        g_ar[0][0][w] = r1;
        g_al[0][1][w] = r2;
        g_ar[0][1][w] = r3;
    }
}

// ---------------- fused GAT agg (both graphs per warp) + node transform epilogue ----------------
// buf: input hh/al/ar buffer; writes buf^1.  last: write se/sk/cc instead of transform.
__global__ void __launch_bounds__(256) k_agg_fused(
        const float* __restrict__ bias0, const float* __restrict__ bias1,
        const float* __restrict__ Ws, const float* __restrict__ a1s, const float* __restrict__ a2s,
        const float* __restrict__ Wk, const float* __restrict__ a1k, const float* __restrict__ a2k,
        const float* __restrict__ x, int buf, int last) {
    __shared__ __half svh[8][32][HD];   // 16KB staging
    __shared__ float sWs[HD * HD];
    __shared__ float sWk[HD * HD];
    if (!last) {
        for (int i = threadIdx.x; i < HD * HD; i += 256) {
            sWs[i] = Ws[i];
            sWk[i] = Wk[i];
        }
    }
    __syncthreads();
    int wid = threadIdx.x >> 5;
    int lane = threadIdx.x & 31;
    int n = (blockIdx.x * blockDim.x + threadIdx.x) >> 5;
    if (n >= NN) return;
    int p = lane & 15;
    int hw = lane >> 4;
    int nbuf = buf ^ 1;

    float2 res[2];
#pragma unroll
    for (int g = 0; g < 2; g++) {
        const int* __restrict__ csr = g_csr[g];
        const float* __restrict__ al = g_al[buf][g];
        const __half* __restrict__ hh = g_hh[buf][g];
        int start = g_rowptr[g][n], end = g_rowptr[g][n + 1];
        int deg = end - start;
        int cnt = (deg < 32) ? deg : 32;
        int s_c = 0;
        if (lane < deg) s_c = csr[start + lane];

        // stage rows early (async)
        __syncwarp();
        {
            int r4 = lane >> 2;
            int c8 = (lane & 3) * 8;
#pragma unroll
            for (int j = 0; j < 4; j++) {
                int row = j * 8 + r4;
                int s = __shfl_sync(FULL, s_c, row);
                if (row < cnt) cp_async16(&svh[wid][row][c8], &hh[s * HD + c8]);
            }
            cp_commit();
        }

        // softmax weights (no max shift: logits are O(1), exact up to rounding)
        float arn = g_ar[buf][g][n];
        float p_c = 0.f;
        if (lane < deg) {
            float e = al[s_c] + arn;
            e = (e >= 0.f) ? e : LRELU_S * e;
            p_c = __expf(e);
        }
        float ss = p_c;
#pragma unroll
        for (int o = 16; o; o >>= 1) ss += __shfl_xor_sync(FULL, ss, o);

        cp_wait0();
        __syncwarp();

        // consume: half2, half-warps split rows
        float2 acc = make_float2(0.f, 0.f);
        for (int k = 0; k < cnt; k += 2) {
            int row = k + hw;
            float wgt = __shfl_sync(FULL, p_c, row & 31);
            if (row < cnt) {
                float2 f = __half22float2(*(const __half2*)&svh[wid][row][2 * p]);
                acc.x += wgt * f.x;
                acc.y += wgt * f.y;
            }
        }
        acc.x += __shfl_xor_sync(FULL, acc.x, 16);
        acc.y += __shfl_xor_sync(FULL, acc.y, 16);

        // rare slow path: degree > 32 (all lanes iterate same edges)
        if (deg > 32) {
            float ssl = 0.f;
            for (int i = start + 32; i < end; i++) {
                int s = csr[i];
                float e = al[s] + arn;
                e = (e >= 0.f) ? e : LRELU_S * e;
                float pw = __expf(e);
                ssl += pw;
                float2 f = __half22float2(*(const __half2*)&hh[s * HD + 2 * p]);
                acc.x += pw * f.x;
                acc.y += pw * f.y;
            }
            ss += ssl;
        }

        const float* bias = g ? bias1 : bias0;
        float inv = 1.f / (ss + 1e-16f);
        float2 b2 = *(const float2*)&bias[2 * p];
        float r0 = acc.x * inv + b2.x; r0 = (r0 >= 0.f) ? r0 : PRELU_S * r0;
        float r1 = acc.y * inv + b2.y; r1 = (r1 >= 0.f) ? r1 : PRELU_S * r1;
        res[g] = make_float2(r0, r1);
    }

    if (last) {
        if (lane < 16) {
            *(float2*)&g_se[n * HD + 2 * p] = res[0];
            *(float2*)&g_sk[n * HD + 2 * p] = res[1];
            float xv = x[n];
            *(__half2*)&g_cc[n][2 * p]      = __floats2half2_rn(res[0].x * xv, res[0].y * xv);
            *(__half2*)&g_cc[n][HD + 2 * p] = __floats2half2_rn(res[1].x * xv, res[1].y * xv);
        }
        return;
    }

    // transform epilogue: c = se + sk (registers); h = c @ W; al/ar dots
    float2 c2 = make_float2(res[0].x + res[1].x, res[0].y + res[1].y);
    float2 accS = make_float2(0.f, 0.f), accK = make_float2(0.f, 0.f);
#pragma unroll
    for (int q = 0; q < 16; q++) {
        float cx = __shfl_sync(FULL, c2.x, q);
        float cy = __shfl_sync(FULL, c2.y, q);
        float2 w0 = *(const float2*)&sWs[(2 * q) * HD + 2 * p];
        float2 w1 = *(const float2*)&sWs[(2 * q + 1) * HD + 2 * p];
        accS.x += cx * w0.x + cy * w1.x;
        accS.y += cx * w0.y + cy * w1.y;
        float2 k0 = *(const float2*)&sWk[(2 * q) * HD + 2 * p];
        float2 k1 = *(const float2*)&sWk[(2 * q + 1) * HD + 2 * p];
        accK.x += cx * k0.x + cy * k1.x;
        accK.y += cx * k0.y + cy * k1.y;
    }
    float2 va1s = *(const float2*)&a1s[2 * p];
    float2 va2s = *(const float2*)&a2s[2 * p];
    float2 va1k = *(const float2*)&a1k[2 * p];
    float2 va2k = *(const float2*)&a2k[2 * p];
    float r0 = accS.x * va1s.x + accS.y * va1s.y;
    float r1 = accS.x * va2s.x + accS.y * va2s.y;
    float r2 = accK.x * va1k.x + accK.y * va1k.y;
    float r3 = accK.x * va2k.x + accK.y * va2k.y;
#pragma unroll
    for (int o = 8; o; o >>= 1) {   // values replicated across half-warps; reduce within half-warp
        r0 += __shfl_xor_sync(FULL, r0, o);
        r1 += __shfl_xor_sync(FULL, r1, o);
        r2 += __shfl_xor_sync(FULL, r2, o);
        r3 += __shfl_xor_sync(FULL, r3, o);
    }
    if (lane == 0) {
        g_al[nbuf][0][n] = r0;
        g_ar[nbuf][0][n] = r1;
        g_al[nbuf][1][n] = r2;
        g_ar[nbuf][1][n] = r3;
    }
    if (lane < 16) {
        *(__half2*)&g_hh[nbuf][0][n * HD + 2 * p] = __floats2half2_rn(accS.x, accS.y);
        *(__half2*)&g_hh[nbuf][1][n * HD + 2 * p] = __floats2half2_rn(accK.x, accK.y);
    }
}

// ---------------- final head: premultiplied cc rows, unweighted sum ----------------
__global__ void __launch_bounds__(256) k_final(
                        const float* __restrict__ Wos, const float* __restrict__ bos,
                        const float* __restrict__ Wok, const float* __restrict__ bok,
                        const float* __restrict__ Wd1, const float* __restrict__ bd1,
                        float* __restrict__ out) {
    __shared__ __half svh[8][32][2 * HD];   // 32KB: packed cc rows
    int wid = threadIdx.x >> 5;
    int lane = threadIdx.x & 31;
    int w = (blockIdx.x * blockDim.x + threadIdx.x) >> 5;
    if (w >= NN) return;

    float2 c2;
    if (lane < 16) c2 = *(const float2*)&g_se[w * HD + 2 * lane];
    else           c2 = *(const float2*)&g_sk[w * HD + 2 * (lane - 16)];

    float4 wos = *(const float4*)&Wos[4 * lane];
    float4 wok = *(const float4*)&Wok[4 * lane];
    float d00 = c2.x * wos.x + c2.y * wos.z;
    float d01 = c2.x * wos.y + c2.y * wos.w;
    float d10 = c2.x * wok.x + c2.y * wok.z;
    float d11 = c2.x * wok.y + c2.y * wok.w;
#pragma unroll
    for (int o = 16; o; o >>= 1) {
        d00 += __shfl_xor_sync(FULL, d00, o);
        d01 += __shfl_xor_sync(FULL, d01, o);
        d10 += __shfl_xor_sync(FULL, d10, o);
        d11 += __shfl_xor_sync(FULL, d11, o);
    }

    float2 agg[2];
#pragma unroll
    for (int g = 0; g < 2; g++) {
        const int* __restrict__ csr = g_csr[g];
        int st = g_rowptr[g][w], en = g_rowptr[g][w + 1];
        int deg = en - st;
        int cnt = (deg < 32) ? deg : 32;
        int s_c = 0;
        if (lane < deg) s_c = csr[st + lane];

        __syncwarp();
        int r = lane >> 3;
        int c = (lane & 7) * 8;
#pragma unroll
        for (int j = 0; j < 8; j++) {
            int row = j * 4 + r;
            int s = __shfl_sync(FULL, s_c, row);
            if (row < cnt) cp_async16(&svh[wid][row][c], &g_cc[s][c]);
        }
        cp_commit();
        cp_wait0();
        __syncwarp();

        float2 a = make_float2(0.f, 0.f);
        for (int k = 0; k < cnt; k++) {
            float2 f = __half22float2(*(const __half2*)&svh[wid][k][2 * lane]);
            a.x += f.x;
            a.y += f.y;
        }
        for (int i = st + 32; i < en; i++) {
            int s = csr[i];
            float2 f = __half22float2(*(const __half2*)&g_cc[s][2 * lane]);
            a.x += f.x;
            a.y += f.y;
        }
        agg[g] = a;
    }

    float e1sx = agg[0].x + 0.5f * c2.x; e1sx = (e1sx > 0.f) ? e1sx : 0.f;
    float e1sy = agg[0].y + 0.5f * c2.y; e1sy = (e1sy > 0.f) ? e1sy : 0.f;
    float e1kx = agg[1].x + 0.5f * c2.x; e1kx = (e1kx > 0.f) ? e1kx : 0.f;
    float e1ky = agg[1].y + 0.5f * c2.y; e1ky = (e1ky > 0.f) ? e1ky : 0.f;

    float tx = e1sx + e1kx;
    float ty = e1sy + e1ky;
    float4 wd = *(const float4*)&Wd1[4 * lane];
    float g0 = tx * wd.x + ty * wd.z;
    float g1 = tx * wd.y + ty * wd.w;
#pragma unroll
    for (int o = 16; o; o >>= 1) {
        g0 += __shfl_xor_sync(FULL, g0, o);
        g1 += __shfl_xor_sync(FULL, g1, o);
    }

    if (lane == 0) {
        float s0 = d00 + bos[0]; s0 = (s0 > 0.f) ? s0 : 0.f;
        float s1 = d01 + bos[1]; s1 = (s1 > 0.f) ? s1 : 0.f;
        float k0 = d10 + bok[0]; k0 = (k0 > 0.f) ? k0 : 0.f;
        float k1 = d11 + bok[1]; k1 = (k1 > 0.f) ? k1 : 0.f;
        out[w * 4 + 0] = 0.5f * (s0 + k0);
        out[w * 4 + 1] = 0.5f * (s1 + k1);
        float f2 = g0 + bd1[0];
        float f3 = g1 + bd1[1];
        out[w * 4 + 2] = (f2 > 0.f) ? f2 : 0.f;
        out[w * 4 + 3] = (f3 > 0.f) ? f3 : 0.f;
    }
}

// ---------------- launch ----------------
extern "C" void kernel_launch(void* const* d_in, const int* in_sizes, int n_in,
                              void* d_out, int out_size) {
    const float* x        = (const float*)d_in[0];
    const int*   sei      = (const int*)d_in[1];
    const int*   kei      = (const int*)d_in[2];
    const float* W_in_src = (const float*)d_in[3];
    const float* b_in_src = (const float*)d_in[4];
    const float* a1_in_src= (const float*)d_in[5];
    const float* a2_in_src= (const float*)d_in[6];
    const float* W_in_snk = (const float*)d_in[7];
    const float* b_in_snk = (const float*)d_in[8];
    const float* a1_in_snk= (const float*)d_in[9];
    const float* a2_in_snk= (const float*)d_in[10];
    const float* W_src    = (const float*)d_in[11];
    const float* b_src    = (const float*)d_in[12];
    const float* a1_src   = (const float*)d_in[13];
    const float* a2_src   = (const float*)d_in[14];
    const float* W_snk    = (const float*)d_in[15];
    const float* b_snk    = (const float*)d_in[16];
    const float* a1_snk   = (const float*)d_in[17];
    const float* a2_snk   = (const float*)d_in[18];
    const float* W_o_src  = (const float*)d_in[19];
    const float* b_o_src  = (const float*)d_in[20];
    const float* W_o_snk  = (const float*)d_in[21];
    const float* b_o_snk  = (const float*)d_in[22];
    const float* W_d1     = (const float*)d_in[23];
    const float* b_d1     = (const float*)d_in[24];
    float* out = (float*)d_out;

    const int* s0 = sei;
    const int* dd0 = sei + EE;
    const int* s1 = kei;
    const int* dd1 = kei + EE;

    const int TB = 256;

    k_degree<<<(EE + TB - 1) / TB, TB>>>(dd0, dd1);
    {
        dim3 g(SCAN_NB, 2);
        k_scan1<<<g, 512>>>();
    }
    {
        dim3 g((NN + TB - 1) / TB, 2);
        k_scan3<<<g, TB>>>();
    }
    k_fill_t0<<<FILL_BLOCKS + T0_BLOCKS, TB>>>(s0, dd0, s1, dd1, x,
                                               W_in_src, a1_in_src, a2_in_src,
                                               W_in_snk, a1_in_snk, a2_in_snk);

    int node_blocks = (NN * 32 + TB - 1) / TB;

    for (int L = 0; L < 5; L++) {
        const float* bb0 = (L == 0) ? b_in_src : b_src + (L - 1) * HD;
        const float* bb1 = (L == 0) ? b_in_snk : b_snk + (L - 1) * HD;
        int last = (L == 4);
        const float* Ws  = last ? W_src  : W_src  + L * HD * HD;
        const float* Wk  = last ? W_snk  : W_snk  + L * HD * HD;
        const float* a1s = last ? a1_src : a1_src + L * HD;
        const float* a2s = last ? a2_src : a2_src + L * HD;
        const float* a1k = last ? a1_snk : a1_snk + L * HD;
        const float* a2k = last ? a2_snk : a2_snk + L * HD;
        k_agg_fused<<<node_blocks, TB>>>(bb0, bb1, Ws, a1s, a2s, Wk, a1k, a2k,
                                         x, L & 1, last);
    }

    k_final<<<node_blocks, TB>>>(W_o_src, b_o_src, W_o_snk, b_o_snk, W_d1, b_d1, out);
}